// round 9
// baseline (speedup 1.0000x reference)
#include <cuda_runtime.h>
#include <cuda_bf16.h>
#include <cstdint>

#define NN 20000
#define EE 320000

// ================= static scratch =================
__device__ __align__(16) float g_A[NN * 1536];    // GEMM fp32 out (z=0)
__device__ __align__(16) float g_B[NN * 1536];    // GEMM fp32 out (z=1)
// bf16 hi/lo split activation buffers (ping-pong)
__device__ __align__(16) __nv_bfloat16 g_Hh[NN * 1536];
__device__ __align__(16) __nv_bfloat16 g_Hl[NN * 1536];
__device__ __align__(16) __nv_bfloat16 g_H2h[NN * 1536];
__device__ __align__(16) __nv_bfloat16 g_H2l[NN * 1536];
// bf16 transposed-split weights, manual offsets (total 5505024 elems)
__device__ __align__(16) __nv_bfloat16 g_Wh[5505024];
__device__ __align__(16) __nv_bfloat16 g_Wlo[5505024];
__device__ int   g_deg[NN];
__device__ int   g_fill[NN];
__device__ int   g_rowptr[NN + 1];
__device__ int   g_col[EE];
__device__ float g_dinv[NN];

// ================= helpers (baseline PTX, sm_80+) =================
__device__ __forceinline__ uint32_t smem_u32(const void* p) {
    uint32_t a;
    asm("{ .reg .u64 t; cvta.to.shared.u64 t, %1; cvt.u32.u64 %0, t; }" : "=r"(a) : "l"(p));
    return a;
}
__device__ __forceinline__ void ldm_x4(uint32_t* r, uint32_t addr) {
    asm volatile("ldmatrix.sync.aligned.m8n8.x4.shared.b16 {%0,%1,%2,%3}, [%4];"
        : "=r"(r[0]), "=r"(r[1]), "=r"(r[2]), "=r"(r[3]) : "r"(addr));
}
__device__ __forceinline__ void mma16816(float* c, const uint32_t* a, const uint32_t* b) {
    asm volatile("mma.sync.aligned.m16n8k16.row.col.f32.bf16.bf16.f32 "
        "{%0,%1,%2,%3}, {%4,%5,%6,%7}, {%8,%9}, {%0,%1,%2,%3};"
        : "+f"(c[0]), "+f"(c[1]), "+f"(c[2]), "+f"(c[3])
        : "r"(a[0]), "r"(a[1]), "r"(a[2]), "r"(a[3]), "r"(b[0]), "r"(b[1]));
}
__device__ __forceinline__ uint32_t sw128(uint32_t off) {
    return off ^ ((off >> 3) & 0x70);
}
__device__ __forceinline__ uint32_t pack_bf2(float a, float b) {
    __nv_bfloat162 v = __halves2bfloat162(__float2bfloat16(a), __float2bfloat16(b));
    return *(uint32_t*)&v;
}
#define CP_ASYNC16(saddr, gptr) \
    asm volatile("cp.async.cg.shared.global [%0], [%1], 16;" :: "r"(saddr), "l"(gptr))
#define CP_COMMIT() asm volatile("cp.async.commit_group;")
#define CP_WAIT0()  asm volatile("cp.async.wait_group 0;")

// ================= CSR construction (edge_index int32) =================
__global__ void zero_counts_kernel() {
    int i = blockIdx.x * blockDim.x + threadIdx.x;
    if (i < NN) { g_deg[i] = 0; g_fill[i] = 0; }
}
__global__ void count_deg_kernel(const int* __restrict__ ei) {
    int e = blockIdx.x * blockDim.x + threadIdx.x;
    if (e < EE) {
        int dst = ei[EE + e];
        if ((unsigned)dst < NN) atomicAdd(&g_deg[dst], 1);
    }
}
__global__ void scan_deg_kernel() {
    __shared__ int sh[1024];
    int tid = threadIdx.x;
    int carry = 0;
    if (tid == 0) g_rowptr[0] = 0;
    for (int base = 0; base < NN; base += 1024) {
        int i = base + tid;
        int v = (i < NN) ? g_deg[i] : 0;
        sh[tid] = v;
        __syncthreads();
        for (int off = 1; off < 1024; off <<= 1) {
            int t = (tid >= off) ? sh[tid - off] : 0;
            __syncthreads();
            sh[tid] += t;
            __syncthreads();
        }
        if (i < NN) {
            g_rowptr[i + 1] = carry + sh[tid];
            g_dinv[i] = 1.0f / fmaxf((float)v, 1.0f);
        }
        int last = sh[1023];
        __syncthreads();
        carry += last;
    }
}
__global__ void fill_csr_kernel(const int* __restrict__ ei) {
    int e = blockIdx.x * blockDim.x + threadIdx.x;
    if (e < EE) {
        int src = ei[e];
        int dst = ei[EE + e];
        if ((unsigned)dst < NN && (unsigned)src < NN) {
            int p = atomicAdd(&g_fill[dst], 1);
            g_col[g_rowptr[dst] + p] = src;
        }
    }
}

// ============ weight prep: tiled transpose + bf16 hi/lo split ============
// dest[off + n*K2 + kofs + k] = split(W[k*N + n]); K,N multiples of 32
__global__ void wprep_kernel(const float* __restrict__ W, int K, int N,
                             int off, int kofs, int K2) {
    __shared__ float tile[32][33];
    const int k0 = blockIdx.x * 32;
    const int n0 = blockIdx.y * 32;
    const int tx = threadIdx.x, ty = threadIdx.y;   // 32 x 8
    // coalesced read: consecutive tx -> consecutive n
#pragma unroll
    for (int r = 0; r < 4; r++)
        tile[ty + r * 8][tx] = W[(size_t)(k0 + ty + r * 8) * N + n0 + tx];
    __syncthreads();
    // coalesced write: consecutive tx -> consecutive k
#pragma unroll
    for (int r = 0; r < 4; r++) {
        int n = n0 + ty + r * 8;
        float w = tile[tx][ty + r * 8];
        __nv_bfloat16 hi = __float2bfloat16(w);
        size_t d = (size_t)off + (size_t)n * K2 + kofs + k0 + tx;
        g_Wh[d] = hi;
        g_Wlo[d] = __float2bfloat16(w - __bfloat162float(hi));
    }
}

// split x into cols [768..1535] of buf0 rows (stride 1536)
__global__ void split_x_kernel(const float* __restrict__ x) {
    int idx = blockIdx.x * blockDim.x + threadIdx.x;
    if (idx >= NN * 768) return;
    int n = idx / 768, c = idx - n * 768;
    float w = x[idx];
    __nv_bfloat16 hi = __float2bfloat16(w);
    size_t d = (size_t)n * 1536 + 768 + c;
    g_Hh[d] = hi;
    g_Hl[d] = __float2bfloat16(w - __bfloat162float(hi));
}

// mean-aggregate x rows -> split -> cols [0..767] of buf0 rows (stride 1536)
__global__ __launch_bounds__(192) void aggx_kernel(const float* __restrict__ x) {
    const int node = blockIdx.x;
    const int tid = threadIdx.x;
    const int s = g_rowptr[node];
    const int e = g_rowptr[node + 1];
    float4 acc = make_float4(0.f, 0.f, 0.f, 0.f);
    __shared__ int nb[192];
    for (int base = s; base < e; base += 192) {
        int cnt = min(192, e - base);
        if (tid < cnt) nb[tid] = g_col[base + tid];
        __syncthreads();
        for (int j = 0; j < cnt; j++) {
            float4 v = ((const float4*)(x + (size_t)nb[j] * 768))[tid];
            acc.x += v.x; acc.y += v.y; acc.z += v.z; acc.w += v.w;
        }
        __syncthreads();
    }
    const float di = g_dinv[node];
    acc.x *= di; acc.y *= di; acc.z *= di; acc.w *= di;
    float hx = __bfloat162float(__float2bfloat16(acc.x));
    float hy = __bfloat162float(__float2bfloat16(acc.y));
    float hz = __bfloat162float(__float2bfloat16(acc.z));
    float hw = __bfloat162float(__float2bfloat16(acc.w));
    uint2 hp = make_uint2(pack_bf2(acc.x, acc.y), pack_bf2(acc.z, acc.w));
    uint2 lp = make_uint2(pack_bf2(acc.x - hx, acc.y - hy), pack_bf2(acc.z - hz, acc.w - hw));
    size_t d = (size_t)node * 1536 + tid * 4;
    *(uint2*)(g_Hh + d) = hp;
    *(uint2*)(g_Hl + d) = lp;
}

// ================= HMMA GEMM: BM=256, BN=128, BK=64, 2-stage =================
// AB: 0 -> A from g_Hh/g_Hl, 1 -> A from g_H2h/g_H2l
// EPI: 0 -> fp32 out to (z ? g_B : g_A); gridDim.z = 2
// EPI: 1 -> fused bias+relu+split out to the OTHER buffer pair; gridDim.z = 1
// stage layout: Ah(32K) | Al(32K) | Bh(16K) | Bl(16K) = 96KB
#define STG2 98304
template <int AB, int EPI>
__global__ __launch_bounds__(256) void bgemm_kernel(
    int woff_l, int woff_r, const float* __restrict__ bias,
    int M, int Kd, int Nd)
{
    extern __shared__ __align__(1024) uint8_t dsm[];
    const __nv_bfloat16* Ahp = AB ? g_H2h : g_Hh;
    const __nv_bfloat16* Alp = AB ? g_H2l : g_Hl;
    const int tid = threadIdx.x;
    const int wid = tid >> 5;
    const int lane = tid & 31;
    const int m0 = blockIdx.y * 256;
    const int n0 = blockIdx.x * 128;
    const int woff = blockIdx.z ? woff_r : woff_l;
    const int warp_m = (wid & 3) * 64;   // 4 m-warps
    const int warp_n = (wid >> 2) * 64;  // 2 n-warps
    const uint32_t sb = smem_u32(dsm);

    // A loads: thread -> row tid (0..255), 8 hi + 8 lo cp.async (128B each side)
    const int arow = min(m0 + tid, M - 1);
    const __nv_bfloat16* gAh = Ahp + (size_t)arow * Kd;
    const __nv_bfloat16* gAl = Alp + (size_t)arow * Kd;
    // B loads: row tid&127, half tid>>7 (32 elems = 64B)
    const int brow = tid & 127;
    const int bhalf = tid >> 7;
    const __nv_bfloat16* gBh = g_Wh + woff + (size_t)(n0 + brow) * Kd + bhalf * 32;
    const __nv_bfloat16* gBl = g_Wlo + woff + (size_t)(n0 + brow) * Kd + bhalf * 32;
    const uint32_t abase = tid * 128;
    const uint32_t bbase = brow * 128 + bhalf * 64;

    float acc[4][8][4];
#pragma unroll
    for (int mi = 0; mi < 4; mi++)
#pragma unroll
        for (int ni = 0; ni < 8; ni++)
#pragma unroll
            for (int qq = 0; qq < 4; qq++) acc[mi][ni][qq] = 0.f;

    const int sub = lane >> 3;
    const int lr = lane & 7;
    const int nch = Kd >> 6;

#define ISSUE_CHUNK(stadr, kofs) do { \
        uint32_t _sAh = (stadr), _sAl = _sAh + 32768, _sBh = _sAh + 65536, _sBl = _sAh + 81920; \
        _Pragma("unroll") \
        for (int j = 0; j < 8; j++) { \
            uint32_t o = sw128(abase + j * 16); \
            CP_ASYNC16(_sAh + o, gAh + (kofs) + j * 8); \
            CP_ASYNC16(_sAl + o, gAl + (kofs) + j * 8); \
        } \
        _Pragma("unroll") \
        for (int j = 0; j < 4; j++) { \
            uint32_t o = sw128(bbase + j * 16); \
            CP_ASYNC16(_sBh + o, gBh + (kofs) + j * 8); \
            CP_ASYNC16(_sBl + o, gBl + (kofs) + j * 8); \
        } \
    } while (0)

    ISSUE_CHUNK(sb, 0);
    CP_COMMIT();

    int st = 0;
    for (int ch = 0; ch < nch; ch++) {
        CP_WAIT0();
        __syncthreads();
        if (ch + 1 < nch) {
            ISSUE_CHUNK(sb + (st ^ 1) * STG2, (ch + 1) << 6);
            CP_COMMIT();
        }

        const uint32_t sAh = sb + st * STG2;
        const uint32_t sAl = sAh + 32768;
        const uint32_t sBh = sAh + 65536;
        const uint32_t sBl = sAh + 81920;

#pragma unroll
        for (int ks = 0; ks < 4; ks++) {
            uint32_t bh[4][4], bl[4][4];
#pragma unroll
            for (int np = 0; np < 4; np++) {
                int row = warp_n + np * 16 + (sub >> 1) * 8 + lr;
                uint32_t kb = ks * 32 + (sub & 1) * 16;
                uint32_t o = sw128(row * 128 + kb);
                ldm_x4(bh[np], sBh + o);
                ldm_x4(bl[np], sBl + o);
            }
#pragma unroll
            for (int mi = 0; mi < 4; mi++) {
                uint32_t ah[4], al[4];
                int row = warp_m + mi * 16 + (sub & 1) * 8 + lr;
                uint32_t kb = ks * 32 + (sub >> 1) * 16;
                uint32_t o = sw128(row * 128 + kb);
                ldm_x4(ah, sAh + o);
                ldm_x4(al, sAl + o);
#pragma unroll
                for (int ni = 0; ni < 8; ni++) {
                    const uint32_t* ph = &bh[ni >> 1][(ni & 1) * 2];
                    const uint32_t* pl = &bl[ni >> 1][(ni & 1) * 2];
                    mma16816(acc[mi][ni], ah, ph);
                    mma16816(acc[mi][ni], ah, pl);
                    mma16816(acc[mi][ni], al, ph);
                }
            }
        }
        st ^= 1;
    }

    // ---- epilogue ----
    const int g = lane >> 2;
    const int t = lane & 3;
    if constexpr (EPI == 0) {
        float* C = blockIdx.z ? g_B : g_A;
#pragma unroll
        for (int mi = 0; mi < 4; mi++) {
            int r0 = m0 + warp_m + mi * 16 + g;
            int r1 = r0 + 8;
#pragma unroll
            for (int ni = 0; ni < 8; ni++) {
                int col = n0 + warp_n + ni * 8 + t * 2;
                if (r0 < M) *(float2*)(C + (size_t)r0 * Nd + col) = make_float2(acc[mi][ni][0], acc[mi][ni][1]);
                if (r1 < M) *(float2*)(C + (size_t)r1 * Nd + col) = make_float2(acc[mi][ni][2], acc[mi][ni][3]);
            }
        }
    } else {
        __nv_bfloat16* Oh = AB ? g_Hh : g_H2h;
        __nv_bfloat16* Ol = AB ? g_Hl : g_H2l;
#pragma unroll
        for (int mi = 0; mi < 4; mi++) {
            int r0 = m0 + warp_m + mi * 16 + g;
            int r1 = r0 + 8;
#pragma unroll
            for (int ni = 0; ni < 8; ni++) {
                int col = n0 + warp_n + ni * 8 + t * 2;
                float b0 = bias[col], b1v = bias[col + 1];
                float v0 = fmaxf(acc[mi][ni][0] + b0, 0.f);
                float v1 = fmaxf(acc[mi][ni][1] + b1v, 0.f);
                float v2 = fmaxf(acc[mi][ni][2] + b0, 0.f);
                float v3 = fmaxf(acc[mi][ni][3] + b1v, 0.f);
                float h0 = __bfloat162float(__float2bfloat16(v0));
                float h1 = __bfloat162float(__float2bfloat16(v1));
                float h2 = __bfloat162float(__float2bfloat16(v2));
                float h3 = __bfloat162float(__float2bfloat16(v3));
                if (r0 < M) {
                    *(uint32_t*)(Oh + (size_t)r0 * Nd + col) = pack_bf2(v0, v1);
                    *(uint32_t*)(Ol + (size_t)r0 * Nd + col) = pack_bf2(v0 - h0, v1 - h1);
                }
                if (r1 < M) {
                    *(uint32_t*)(Oh + (size_t)r1 * Nd + col) = pack_bf2(v2, v3);
                    *(uint32_t*)(Ol + (size_t)r1 * Nd + col) = pack_bf2(v2 - h2, v3 - h3);
                }
            }
        }
    }
}

// ================= small-N GEMM for the final 256->5 linear =================
__global__ void gemm_small_kernel(const float* __restrict__ Aext,
                                  const float* __restrict__ W,
                                  int zsel, int M, int Kd, int Nd)
{
    float* C = zsel ? g_B : g_A;
    int idx = blockIdx.x * blockDim.x + threadIdx.x;
    if (idx >= M * Nd) return;
    int row = idx / Nd, c = idx % Nd;
    const float* a = Aext + (size_t)row * Kd;
    float acc = 0.f;
    for (int k = 0; k < Kd; k++) acc += a[k] * W[k * Nd + c];
    C[idx] = acc;
}

// ================= combine (layers 2-4): r = relu(di*agg(g_A) + g_B + b) ===
template <int F, int OM>
__global__ void combine_kernel(const float* __restrict__ bias,
                               float* __restrict__ outExt)
{
    constexpr int NT = F / 4;
    const int node = blockIdx.x;
    const int tid = threadIdx.x;
    const int s = g_rowptr[node];
    const int e = g_rowptr[node + 1];

    float4 acc = make_float4(0.f, 0.f, 0.f, 0.f);
    __shared__ int nb[NT];
    for (int base = s; base < e; base += NT) {
        int cnt = min(NT, e - base);
        if (tid < cnt) nb[tid] = g_col[base + tid];
        __syncthreads();
        for (int j = 0; j < cnt; j++) {
            float4 v = ((const float4*)(g_A + (size_t)nb[j] * F))[tid];
            acc.x += v.x; acc.y += v.y; acc.z += v.z; acc.w += v.w;
        }
        __syncthreads();
    }

    const float di = g_dinv[node];
    float4 sv = ((const float4*)(g_B + (size_t)node * F))[tid];
    float4 bv = ((const float4*)bias)[tid];
    float rx = fmaxf(acc.x * di + sv.x + bv.x, 0.f);
    float ry = fmaxf(acc.y * di + sv.y + bv.y, 0.f);
    float rz = fmaxf(acc.z * di + sv.z + bv.z, 0.f);
    float rw = fmaxf(acc.w * di + sv.w + bv.w, 0.f);

    if constexpr (OM == 0) {
        ((float4*)(outExt + (size_t)node * F))[tid] = make_float4(rx, ry, rz, rw);
    } else {
        __nv_bfloat16* Oh = (OM == 1) ? g_Hh : g_H2h;
        __nv_bfloat16* Ol = (OM == 1) ? g_Hl : g_H2l;
        float hx = __bfloat162float(__float2bfloat16(rx));
        float hy = __bfloat162float(__float2bfloat16(ry));
        float hz = __bfloat162float(__float2bfloat16(rz));
        float hw = __bfloat162float(__float2bfloat16(rw));
        size_t d = (size_t)node * F + tid * 4;
        *(uint2*)(Oh + d) = make_uint2(pack_bf2(rx, ry), pack_bf2(rz, rw));
        *(uint2*)(Ol + d) = make_uint2(pack_bf2(rx - hx, ry - hy), pack_bf2(rz - hz, rw - hw));
    }
}

__global__ void combine5_kernel(const float* __restrict__ bias,
                                float* __restrict__ out)
{
    int node = blockIdx.x * 4 + (threadIdx.x >> 5);
    if (node >= NN) return;
    int lane = threadIdx.x & 31;
    if (lane >= 5) return;
    int s = g_rowptr[node], e = g_rowptr[node + 1];
    float acc = 0.f;
    for (int j = s; j < e; j++) acc += g_A[g_col[j] * 5 + lane];
    out[node * 5 + lane] = acc * g_dinv[node] + g_B[node * 5 + lane] + bias[lane];
}

// ================= launch =================
extern "C" void kernel_launch(void* const* d_in, const int* in_sizes, int n_in,
                              void* d_out, int out_size)
{
    const float* x  = (const float*)d_in[0];
    const int*   ei = (const int*)d_in[1];
    const float* Wl1 = (const float*)d_in[2];
    const float* Wr1 = (const float*)d_in[3];
    const float* b1  = (const float*)d_in[4];
    const float* Wl2 = (const float*)d_in[5];
    const float* Wr2 = (const float*)d_in[6];
    const float* b2  = (const float*)d_in[7];
    const float* Wl3 = (const float*)d_in[8];
    const float* Wr3 = (const float*)d_in[9];
    const float* b3  = (const float*)d_in[10];
    const float* Wl4 = (const float*)d_in[11];
    const float* Wr4 = (const float*)d_in[12];
    const float* b4  = (const float*)d_in[13];
    const float* Wl5 = (const float*)d_in[14];
    const float* Wr5 = (const float*)d_in[15];
    const float* b5  = (const float*)d_in[16];

    float* out = (float*)d_out;
    float* out_h   = out;                      // [NN, 256]
    float* out_cls = out + (size_t)NN * 256;   // [NN, 5]

    const int SMEM_SZ = 2 * STG2;   // 192 KB
    cudaFuncSetAttribute(bgemm_kernel<0, 1>, cudaFuncAttributeMaxDynamicSharedMemorySize, SMEM_SZ);
    cudaFuncSetAttribute(bgemm_kernel<1, 0>, cudaFuncAttributeMaxDynamicSharedMemorySize, SMEM_SZ);
    cudaFuncSetAttribute(bgemm_kernel<0, 0>, cudaFuncAttributeMaxDynamicSharedMemorySize, SMEM_SZ);

    // ---- CSR build ----
    zero_counts_kernel<<<(NN + 255) / 256, 256>>>();
    count_deg_kernel<<<(EE + 255) / 256, 256>>>(ei);
    scan_deg_kernel<<<1, 1024>>>();
    fill_csr_kernel<<<(EE + 255) / 256, 256>>>(ei);

    // ---- weight prep (tiled transpose + split) ----
    const int OFF1 = 0;
    const int OFF2L = 2359296, OFF2R = 3538944;
    const int OFF3L = 4718592, OFF3R = 5013504;
    const int OFF4L = 5308416, OFF4R = 5406720;
    dim3 tb(32, 8);
    wprep_kernel<<<dim3(768 / 32, 1536 / 32), tb>>>(Wl1, 768, 1536, OFF1, 0, 1536);
    wprep_kernel<<<dim3(768 / 32, 1536 / 32), tb>>>(Wr1, 768, 1536, OFF1, 768, 1536);
    wprep_kernel<<<dim3(1536 / 32, 768 / 32), tb>>>(Wl2, 1536, 768, OFF2L, 0, 1536);
    wprep_kernel<<<dim3(1536 / 32, 768 / 32), tb>>>(Wr2, 1536, 768, OFF2R, 0, 1536);
    wprep_kernel<<<dim3(768 / 32, 384 / 32), tb>>>(Wl3, 768, 384, OFF3L, 0, 768);
    wprep_kernel<<<dim3(768 / 32, 384 / 32), tb>>>(Wr3, 768, 384, OFF3R, 0, 768);
    wprep_kernel<<<dim3(384 / 32, 256 / 32), tb>>>(Wl4, 384, 256, OFF4L, 0, 384);
    wprep_kernel<<<dim3(384 / 32, 256 / 32), tb>>>(Wr4, 384, 256, OFF4R, 0, 384);

    // ---- input prep ----
    split_x_kernel<<<(NN * 768 + 255) / 256, 256>>>(x);
    aggx_kernel<<<NN, 192>>>(x);

    const int M = NN;
    const int gy = (M + 255) / 256;   // 79

    // ---- Layer 1: fused [agg|x] @ [[Wl],[Wr]] (K=1536) + bias+relu+split ----
    bgemm_kernel<0, 1><<<dim3(12, gy, 1), 256, SMEM_SZ>>>(OFF1, OFF1, b1, M, 1536, 1536);  // -> buf1

    // ---- Layer 2: 1536 -> 768 ----
    bgemm_kernel<1, 0><<<dim3(6, gy, 2), 256, SMEM_SZ>>>(OFF2L, OFF2R, nullptr, M, 1536, 768);
    combine_kernel<768, 1><<<NN, 192>>>(b2, nullptr);     // -> buf0

    // ---- Layer 3: 768 -> 384 ----
    bgemm_kernel<0, 0><<<dim3(3, gy, 2), 256, SMEM_SZ>>>(OFF3L, OFF3R, nullptr, M, 768, 384);
    combine_kernel<384, 2><<<NN, 96>>>(b3, nullptr);      // -> buf1

    // ---- Layer 4: 384 -> 256 (h output fp32) ----
    bgemm_kernel<1, 0><<<dim3(2, gy, 2), 256, SMEM_SZ>>>(OFF4L, OFF4R, nullptr, M, 384, 256);
    combine_kernel<256, 0><<<NN, 64>>>(b4, out_h);        // -> d_out h region

    // ---- Layer 5: 256 -> 5 (no relu) ----
    gemm_small_kernel<<<(NN * 5 + 255) / 256, 256>>>(out_h, Wl5, 0, M, 256, 5);
    gemm_small_kernel<<<(NN * 5 + 255) / 256, 256>>>(out_h, Wr5, 1, M, 256, 5);
    combine5_kernel<<<(NN + 3) / 4, 128>>>(b5, out_cls);
}

// round 10
// speedup vs baseline: 1.2814x; 1.2814x over previous
#include <cuda_runtime.h>
#include <cuda_bf16.h>
#include <cstdint>

#define NN 20000
#define EE 320000

// ================= static scratch =================
__device__ __align__(16) float g_A[NN * 1536];    // GEMM fp32 out (z=0)
__device__ __align__(16) float g_B[NN * 1536];    // GEMM fp32 out (z=1)
// bf16 hi/lo split activation buffers (ping-pong)
__device__ __align__(16) __nv_bfloat16 g_Hh[NN * 1536];
__device__ __align__(16) __nv_bfloat16 g_Hl[NN * 1536];
__device__ __align__(16) __nv_bfloat16 g_H2h[NN * 1536];
__device__ __align__(16) __nv_bfloat16 g_H2l[NN * 1536];
// bf16 transposed-split weights, manual offsets (total 5505024 elems)
__device__ __align__(16) __nv_bfloat16 g_Wh[5505024];
__device__ __align__(16) __nv_bfloat16 g_Wlo[5505024];
__device__ int   g_deg[NN];
__device__ int   g_fill[NN];
__device__ int   g_rowptr[NN + 1];
__device__ int   g_col[EE];
__device__ float g_dinv[NN];

// ================= helpers (baseline PTX, sm_80+) =================
__device__ __forceinline__ uint32_t smem_u32(const void* p) {
    uint32_t a;
    asm("{ .reg .u64 t; cvta.to.shared.u64 t, %1; cvt.u32.u64 %0, t; }" : "=r"(a) : "l"(p));
    return a;
}
__device__ __forceinline__ void ldm_x4(uint32_t* r, uint32_t addr) {
    asm volatile("ldmatrix.sync.aligned.m8n8.x4.shared.b16 {%0,%1,%2,%3}, [%4];"
        : "=r"(r[0]), "=r"(r[1]), "=r"(r[2]), "=r"(r[3]) : "r"(addr));
}
__device__ __forceinline__ void mma16816(float* c, const uint32_t* a, const uint32_t* b) {
    asm volatile("mma.sync.aligned.m16n8k16.row.col.f32.bf16.bf16.f32 "
        "{%0,%1,%2,%3}, {%4,%5,%6,%7}, {%8,%9}, {%0,%1,%2,%3};"
        : "+f"(c[0]), "+f"(c[1]), "+f"(c[2]), "+f"(c[3])
        : "r"(a[0]), "r"(a[1]), "r"(a[2]), "r"(a[3]), "r"(b[0]), "r"(b[1]));
}
__device__ __forceinline__ uint32_t sw128(uint32_t off) {
    return off ^ ((off >> 3) & 0x70);
}
__device__ __forceinline__ uint32_t pack_bf2(float a, float b) {
    __nv_bfloat162 v = __halves2bfloat162(__float2bfloat16(a), __float2bfloat16(b));
    return *(uint32_t*)&v;
}
#define CP_ASYNC16(saddr, gptr) \
    asm volatile("cp.async.cg.shared.global [%0], [%1], 16;" :: "r"(saddr), "l"(gptr))
#define CP_COMMIT() asm volatile("cp.async.commit_group;")
#define CP_WAIT1()  asm volatile("cp.async.wait_group 1;")

// ================= CSR construction (edge_index int32) =================
__global__ void zero_counts_kernel() {
    int i = blockIdx.x * blockDim.x + threadIdx.x;
    if (i < NN) { g_deg[i] = 0; g_fill[i] = 0; }
}
__global__ void count_deg_kernel(const int* __restrict__ ei) {
    int e = blockIdx.x * blockDim.x + threadIdx.x;
    if (e < EE) {
        int dst = ei[EE + e];
        if ((unsigned)dst < NN) atomicAdd(&g_deg[dst], 1);
    }
}
__global__ void scan_deg_kernel() {
    __shared__ int sh[1024];
    int tid = threadIdx.x;
    int carry = 0;
    if (tid == 0) g_rowptr[0] = 0;
    for (int base = 0; base < NN; base += 1024) {
        int i = base + tid;
        int v = (i < NN) ? g_deg[i] : 0;
        sh[tid] = v;
        __syncthreads();
        for (int off = 1; off < 1024; off <<= 1) {
            int t = (tid >= off) ? sh[tid - off] : 0;
            __syncthreads();
            sh[tid] += t;
            __syncthreads();
        }
        if (i < NN) {
            g_rowptr[i + 1] = carry + sh[tid];
            g_dinv[i] = 1.0f / fmaxf((float)v, 1.0f);
        }
        int last = sh[1023];
        __syncthreads();
        carry += last;
    }
}
__global__ void fill_csr_kernel(const int* __restrict__ ei) {
    int e = blockIdx.x * blockDim.x + threadIdx.x;
    if (e < EE) {
        int src = ei[e];
        int dst = ei[EE + e];
        if ((unsigned)dst < NN && (unsigned)src < NN) {
            int p = atomicAdd(&g_fill[dst], 1);
            g_col[g_rowptr[dst] + p] = src;
        }
    }
}

// ============ weight prep: tiled transpose + bf16 hi/lo split ============
__global__ void wprep_kernel(const float* __restrict__ W, int K, int N,
                             int off, int kofs, int K2) {
    __shared__ float tile[32][33];
    const int k0 = blockIdx.x * 32;
    const int n0 = blockIdx.y * 32;
    const int tx = threadIdx.x, ty = threadIdx.y;   // 32 x 8
#pragma unroll
    for (int r = 0; r < 4; r++)
        tile[ty + r * 8][tx] = W[(size_t)(k0 + ty + r * 8) * N + n0 + tx];
    __syncthreads();
#pragma unroll
    for (int r = 0; r < 4; r++) {
        int n = n0 + ty + r * 8;
        float w = tile[tx][ty + r * 8];
        __nv_bfloat16 hi = __float2bfloat16(w);
        size_t d = (size_t)off + (size_t)n * K2 + kofs + k0 + tx;
        g_Wh[d] = hi;
        g_Wlo[d] = __float2bfloat16(w - __bfloat162float(hi));
    }
}

// fused: mean-aggregate neighbors -> split -> cols [0,768);
//        split own x row -> cols [768,1536). Block per node, 192 threads.
__global__ __launch_bounds__(192) void prep_x_kernel(const float* __restrict__ x) {
    const int node = blockIdx.x;
    const int tid = threadIdx.x;
    const int s = g_rowptr[node];
    const int e = g_rowptr[node + 1];
    float4 acc = make_float4(0.f, 0.f, 0.f, 0.f);
    __shared__ int nb[192];
    for (int base = s; base < e; base += 192) {
        int cnt = min(192, e - base);
        if (tid < cnt) nb[tid] = g_col[base + tid];
        __syncthreads();
        for (int j = 0; j < cnt; j++) {
            float4 v = ((const float4*)(x + (size_t)nb[j] * 768))[tid];
            acc.x += v.x; acc.y += v.y; acc.z += v.z; acc.w += v.w;
        }
        __syncthreads();
    }
    const float di = g_dinv[node];
    acc.x *= di; acc.y *= di; acc.z *= di; acc.w *= di;
    {
        float hx = __bfloat162float(__float2bfloat16(acc.x));
        float hy = __bfloat162float(__float2bfloat16(acc.y));
        float hz = __bfloat162float(__float2bfloat16(acc.z));
        float hw = __bfloat162float(__float2bfloat16(acc.w));
        size_t d = (size_t)node * 1536 + tid * 4;
        *(uint2*)(g_Hh + d) = make_uint2(pack_bf2(acc.x, acc.y), pack_bf2(acc.z, acc.w));
        *(uint2*)(g_Hl + d) = make_uint2(pack_bf2(acc.x - hx, acc.y - hy), pack_bf2(acc.z - hz, acc.w - hw));
    }
    {
        float4 v = ((const float4*)(x + (size_t)node * 768))[tid];
        float hx = __bfloat162float(__float2bfloat16(v.x));
        float hy = __bfloat162float(__float2bfloat16(v.y));
        float hz = __bfloat162float(__float2bfloat16(v.z));
        float hw = __bfloat162float(__float2bfloat16(v.w));
        size_t d = (size_t)node * 1536 + 768 + tid * 4;
        *(uint2*)(g_Hh + d) = make_uint2(pack_bf2(v.x, v.y), pack_bf2(v.z, v.w));
        *(uint2*)(g_Hl + d) = make_uint2(pack_bf2(v.x - hx, v.y - hy), pack_bf2(v.z - hz, v.w - hw));
    }
}

// ================= HMMA GEMM (R8 proven: BM=128, BK=64, 3-stage) =================
// AB: 0 -> A from g_Hh/g_Hl, 1 -> A from g_H2h/g_H2l
// EPI: 0 -> fp32 out to (z ? g_B : g_A); gridDim.z = 2, weights woff_l/woff_r
// EPI: 1 -> fused bias+relu+split out to the OTHER buffer pair; gridDim.z = 1
#define STG 65536
#define NSTAGE 3
template <int AB, int EPI>
__global__ __launch_bounds__(256) void bgemm_kernel(
    int woff_l, int woff_r, const float* __restrict__ bias,
    int M, int Kd, int Nd)
{
    extern __shared__ __align__(1024) uint8_t dsm[];
    const __nv_bfloat16* Ah = AB ? g_H2h : g_Hh;
    const __nv_bfloat16* Al = AB ? g_H2l : g_Hl;
    const int tid = threadIdx.x;
    const int wid = tid >> 5;
    const int lane = tid & 31;
    const int m0 = blockIdx.y * 128;
    const int n0 = blockIdx.x * 128;
    const int woff = blockIdx.z ? woff_r : woff_l;
    const int warp_m = (wid & 1) * 64;
    const int warp_n = (wid >> 1) * 32;
    const uint32_t sb = smem_u32(dsm);

    const int lrow = tid >> 1;
    const int q = tid & 1;
    const int arow = min(m0 + lrow, M - 1);
    const __nv_bfloat16* gAh = Ah + (size_t)arow * Kd + q * 32;
    const __nv_bfloat16* gAl = Al + (size_t)arow * Kd + q * 32;
    const __nv_bfloat16* gBh = g_Wh + woff + (size_t)(n0 + lrow) * Kd + q * 32;
    const __nv_bfloat16* gBl = g_Wlo + woff + (size_t)(n0 + lrow) * Kd + q * 32;
    const uint32_t dbase = lrow * 128 + q * 64;

    float acc[4][4][4];
#pragma unroll
    for (int mi = 0; mi < 4; mi++)
#pragma unroll
        for (int ni = 0; ni < 4; ni++)
#pragma unroll
            for (int qq = 0; qq < 4; qq++) acc[mi][ni][qq] = 0.f;

    const int sub = lane >> 3;
    const int lr = lane & 7;
    const int nch = Kd >> 6;

    // prologue: issue chunks 0 and 1 as separate groups
    {
#pragma unroll
        for (int j = 0; j < 4; j++) {
            uint32_t o = sw128(dbase + j * 16);
            CP_ASYNC16(sb + o,         gAh + j * 8);
            CP_ASYNC16(sb + 16384 + o, gAl + j * 8);
            CP_ASYNC16(sb + 32768 + o, gBh + j * 8);
            CP_ASYNC16(sb + 49152 + o, gBl + j * 8);
        }
        CP_COMMIT();
        if (1 < nch) {
            uint32_t s1 = sb + STG;
#pragma unroll
            for (int j = 0; j < 4; j++) {
                uint32_t o = sw128(dbase + j * 16);
                CP_ASYNC16(s1 + o,         gAh + 64 + j * 8);
                CP_ASYNC16(s1 + 16384 + o, gAl + 64 + j * 8);
                CP_ASYNC16(s1 + 32768 + o, gBh + 64 + j * 8);
                CP_ASYNC16(s1 + 49152 + o, gBl + 64 + j * 8);
            }
        }
        CP_COMMIT();
    }

    int st = 0;
    int st2 = 2;
    for (int ch = 0; ch < nch; ch++) {
        CP_WAIT1();
        __syncthreads();

        if (ch + 2 < nch) {
            const int k2 = (ch + 2) << 6;
            uint32_t s2 = sb + st2 * STG;
#pragma unroll
            for (int j = 0; j < 4; j++) {
                uint32_t o = sw128(dbase + j * 16);
                CP_ASYNC16(s2 + o,         gAh + k2 + j * 8);
                CP_ASYNC16(s2 + 16384 + o, gAl + k2 + j * 8);
                CP_ASYNC16(s2 + 32768 + o, gBh + k2 + j * 8);
                CP_ASYNC16(s2 + 49152 + o, gBl + k2 + j * 8);
            }
        }
        CP_COMMIT();

        const uint32_t sAh = sb + st * STG;
        const uint32_t sAl = sAh + 16384;
        const uint32_t sBh = sAh + 32768;
        const uint32_t sBl = sAh + 49152;

#pragma unroll
        for (int ks = 0; ks < 4; ks++) {
            uint32_t ah[4][4], al[4][4];
#pragma unroll
            for (int mi = 0; mi < 4; mi++) {
                int row = warp_m + mi * 16 + (sub & 1) * 8 + lr;
                uint32_t kb = ks * 32 + (sub >> 1) * 16;
                uint32_t o = sw128(row * 128 + kb);
                ldm_x4(ah[mi], sAh + o);
                ldm_x4(al[mi], sAl + o);
            }
            uint32_t bh[2][4], bl[2][4];
#pragma unroll
            for (int np = 0; np < 2; np++) {
                int row = warp_n + np * 16 + (sub >> 1) * 8 + lr;
                uint32_t kb = ks * 32 + (sub & 1) * 16;
                uint32_t o = sw128(row * 128 + kb);
                ldm_x4(bh[np], sBh + o);
                ldm_x4(bl[np], sBl + o);
            }
#pragma unroll
            for (int mi = 0; mi < 4; mi++)
#pragma unroll
                for (int ni = 0; ni < 4; ni++) {
                    const uint32_t* ph = &bh[ni >> 1][(ni & 1) * 2];
                    const uint32_t* pl = &bl[ni >> 1][(ni & 1) * 2];
                    mma16816(acc[mi][ni], ah[mi], ph);
                    mma16816(acc[mi][ni], ah[mi], pl);
                    mma16816(acc[mi][ni], al[mi], ph);
                }
        }
        st = (st == 2) ? 0 : st + 1;
        st2 = (st2 == 2) ? 0 : st2 + 1;
    }

    // ---- epilogue ----
    const int g = lane >> 2;
    const int t = lane & 3;
    if constexpr (EPI == 0) {
        float* C = blockIdx.z ? g_B : g_A;
#pragma unroll
        for (int mi = 0; mi < 4; mi++) {
            int r0 = m0 + warp_m + mi * 16 + g;
            int r1 = r0 + 8;
#pragma unroll
            for (int ni = 0; ni < 4; ni++) {
                int col = n0 + warp_n + ni * 8 + t * 2;
                if (r0 < M) *(float2*)(C + (size_t)r0 * Nd + col) = make_float2(acc[mi][ni][0], acc[mi][ni][1]);
                if (r1 < M) *(float2*)(C + (size_t)r1 * Nd + col) = make_float2(acc[mi][ni][2], acc[mi][ni][3]);
            }
        }
    } else {
        __nv_bfloat16* Oh = AB ? g_Hh : g_H2h;
        __nv_bfloat16* Ol = AB ? g_Hl : g_H2l;
#pragma unroll
        for (int mi = 0; mi < 4; mi++) {
            int r0 = m0 + warp_m + mi * 16 + g;
            int r1 = r0 + 8;
#pragma unroll
            for (int ni = 0; ni < 4; ni++) {
                int col = n0 + warp_n + ni * 8 + t * 2;
                float b0 = bias[col], b1v = bias[col + 1];
                float v0 = fmaxf(acc[mi][ni][0] + b0, 0.f);
                float v1 = fmaxf(acc[mi][ni][1] + b1v, 0.f);
                float v2 = fmaxf(acc[mi][ni][2] + b0, 0.f);
                float v3 = fmaxf(acc[mi][ni][3] + b1v, 0.f);
                float h0 = __bfloat162float(__float2bfloat16(v0));
                float h1 = __bfloat162float(__float2bfloat16(v1));
                float h2 = __bfloat162float(__float2bfloat16(v2));
                float h3 = __bfloat162float(__float2bfloat16(v3));
                if (r0 < M) {
                    *(uint32_t*)(Oh + (size_t)r0 * Nd + col) = pack_bf2(v0, v1);
                    *(uint32_t*)(Ol + (size_t)r0 * Nd + col) = pack_bf2(v0 - h0, v1 - h1);
                }
                if (r1 < M) {
                    *(uint32_t*)(Oh + (size_t)r1 * Nd + col) = pack_bf2(v2, v3);
                    *(uint32_t*)(Ol + (size_t)r1 * Nd + col) = pack_bf2(v2 - h2, v3 - h3);
                }
            }
        }
    }
}

// ================= small-N GEMM for the final 256->5 linear =================
__global__ void gemm_small_kernel(const float* __restrict__ Aext,
                                  const float* __restrict__ W,
                                  int zsel, int M, int Kd, int Nd)
{
    float* C = zsel ? g_B : g_A;
    int idx = blockIdx.x * blockDim.x + threadIdx.x;
    if (idx >= M * Nd) return;
    int row = idx / Nd, c = idx % Nd;
    const float* a = Aext + (size_t)row * Kd;
    float acc = 0.f;
    for (int k = 0; k < Kd; k++) acc += a[k] * W[k * Nd + c];
    C[idx] = acc;
}

// ================= combine (layers 2-4): r = relu(di*agg(g_A) + g_B + b) ===
template <int F, int OM>
__global__ void combine_kernel(const float* __restrict__ bias,
                               float* __restrict__ outExt)
{
    constexpr int NT = F / 4;
    const int node = blockIdx.x;
    const int tid = threadIdx.x;
    const int s = g_rowptr[node];
    const int e = g_rowptr[node + 1];

    float4 acc = make_float4(0.f, 0.f, 0.f, 0.f);
    __shared__ int nb[NT];
    for (int base = s; base < e; base += NT) {
        int cnt = min(NT, e - base);
        if (tid < cnt) nb[tid] = g_col[base + tid];
        __syncthreads();
        for (int j = 0; j < cnt; j++) {
            float4 v = ((const float4*)(g_A + (size_t)nb[j] * F))[tid];
            acc.x += v.x; acc.y += v.y; acc.z += v.z; acc.w += v.w;
        }
        __syncthreads();
    }

    const float di = g_dinv[node];
    float4 sv = ((const float4*)(g_B + (size_t)node * F))[tid];
    float4 bv = ((const float4*)bias)[tid];
    float rx = fmaxf(acc.x * di + sv.x + bv.x, 0.f);
    float ry = fmaxf(acc.y * di + sv.y + bv.y, 0.f);
    float rz = fmaxf(acc.z * di + sv.z + bv.z, 0.f);
    float rw = fmaxf(acc.w * di + sv.w + bv.w, 0.f);

    if constexpr (OM == 0) {
        ((float4*)(outExt + (size_t)node * F))[tid] = make_float4(rx, ry, rz, rw);
    } else {
        __nv_bfloat16* Oh = (OM == 1) ? g_Hh : g_H2h;
        __nv_bfloat16* Ol = (OM == 1) ? g_Hl : g_H2l;
        float hx = __bfloat162float(__float2bfloat16(rx));
        float hy = __bfloat162float(__float2bfloat16(ry));
        float hz = __bfloat162float(__float2bfloat16(rz));
        float hw = __bfloat162float(__float2bfloat16(rw));
        size_t d = (size_t)node * F + tid * 4;
        *(uint2*)(Oh + d) = make_uint2(pack_bf2(rx, ry), pack_bf2(rz, rw));
        *(uint2*)(Ol + d) = make_uint2(pack_bf2(rx - hx, ry - hy), pack_bf2(rz - hz, rw - hw));
    }
}

__global__ void combine5_kernel(const float* __restrict__ bias,
                                float* __restrict__ out)
{
    int node = blockIdx.x * 4 + (threadIdx.x >> 5);
    if (node >= NN) return;
    int lane = threadIdx.x & 31;
    if (lane >= 5) return;
    int s = g_rowptr[node], e = g_rowptr[node + 1];
    float acc = 0.f;
    for (int j = s; j < e; j++) acc += g_A[g_col[j] * 5 + lane];
    out[node * 5 + lane] = acc * g_dinv[node] + g_B[node * 5 + lane] + bias[lane];
}

// ================= launch =================
extern "C" void kernel_launch(void* const* d_in, const int* in_sizes, int n_in,
                              void* d_out, int out_size)
{
    const float* x  = (const float*)d_in[0];
    const int*   ei = (const int*)d_in[1];
    const float* Wl1 = (const float*)d_in[2];
    const float* Wr1 = (const float*)d_in[3];
    const float* b1  = (const float*)d_in[4];
    const float* Wl2 = (const float*)d_in[5];
    const float* Wr2 = (const float*)d_in[6];
    const float* b2  = (const float*)d_in[7];
    const float* Wl3 = (const float*)d_in[8];
    const float* Wr3 = (const float*)d_in[9];
    const float* b3  = (const float*)d_in[10];
    const float* Wl4 = (const float*)d_in[11];
    const float* Wr4 = (const float*)d_in[12];
    const float* b4  = (const float*)d_in[13];
    const float* Wl5 = (const float*)d_in[14];
    const float* Wr5 = (const float*)d_in[15];
    const float* b5  = (const float*)d_in[16];

    float* out = (float*)d_out;
    float* out_h   = out;                      // [NN, 256]
    float* out_cls = out + (size_t)NN * 256;   // [NN, 5]

    const int SMEM_SZ = NSTAGE * STG;   // 192 KB
    cudaFuncSetAttribute(bgemm_kernel<0, 1>, cudaFuncAttributeMaxDynamicSharedMemorySize, SMEM_SZ);
    cudaFuncSetAttribute(bgemm_kernel<1, 0>, cudaFuncAttributeMaxDynamicSharedMemorySize, SMEM_SZ);
    cudaFuncSetAttribute(bgemm_kernel<0, 0>, cudaFuncAttributeMaxDynamicSharedMemorySize, SMEM_SZ);

    // ---- CSR build ----
    zero_counts_kernel<<<(NN + 255) / 256, 256>>>();
    count_deg_kernel<<<(EE + 255) / 256, 256>>>(ei);
    scan_deg_kernel<<<1, 1024>>>();
    fill_csr_kernel<<<(EE + 255) / 256, 256>>>(ei);

    // ---- weight prep (tiled transpose + split) ----
    const int OFF1 = 0;
    const int OFF2L = 2359296, OFF2R = 3538944;
    const int OFF3L = 4718592, OFF3R = 5013504;
    const int OFF4L = 5308416, OFF4R = 5406720;
    dim3 tb(32, 8);
    wprep_kernel<<<dim3(768 / 32, 1536 / 32), tb>>>(Wl1, 768, 1536, OFF1, 0, 1536);
    wprep_kernel<<<dim3(768 / 32, 1536 / 32), tb>>>(Wr1, 768, 1536, OFF1, 768, 1536);
    wprep_kernel<<<dim3(1536 / 32, 768 / 32), tb>>>(Wl2, 1536, 768, OFF2L, 0, 1536);
    wprep_kernel<<<dim3(1536 / 32, 768 / 32), tb>>>(Wr2, 1536, 768, OFF2R, 0, 1536);
    wprep_kernel<<<dim3(768 / 32, 384 / 32), tb>>>(Wl3, 768, 384, OFF3L, 0, 768);
    wprep_kernel<<<dim3(768 / 32, 384 / 32), tb>>>(Wr3, 768, 384, OFF3R, 0, 768);
    wprep_kernel<<<dim3(384 / 32, 256 / 32), tb>>>(Wl4, 384, 256, OFF4L, 0, 384);
    wprep_kernel<<<dim3(384 / 32, 256 / 32), tb>>>(Wr4, 384, 256, OFF4R, 0, 384);

    // ---- input prep: fused agg + self split ----
    prep_x_kernel<<<NN, 192>>>(x);

    const int M = NN;
    const int gy = (M + 127) / 128;   // 157

    // ---- Layer 1: fused [agg|x] @ [[Wl],[Wr]] (K=1536) + bias+relu+split ----
    bgemm_kernel<0, 1><<<dim3(12, gy, 1), 256, SMEM_SZ>>>(OFF1, OFF1, b1, M, 1536, 1536);  // -> buf1

    // ---- Layer 2: 1536 -> 768 ----
    bgemm_kernel<1, 0><<<dim3(6, gy, 2), 256, SMEM_SZ>>>(OFF2L, OFF2R, nullptr, M, 1536, 768);
    combine_kernel<768, 1><<<NN, 192>>>(b2, nullptr);     // -> buf0

    // ---- Layer 3: 768 -> 384 ----
    bgemm_kernel<0, 0><<<dim3(3, gy, 2), 256, SMEM_SZ>>>(OFF3L, OFF3R, nullptr, M, 768, 384);
    combine_kernel<384, 2><<<NN, 96>>>(b3, nullptr);      // -> buf1

    // ---- Layer 4: 384 -> 256 (h output fp32) ----
    bgemm_kernel<1, 0><<<dim3(2, gy, 2), 256, SMEM_SZ>>>(OFF4L, OFF4R, nullptr, M, 384, 256);
    combine_kernel<256, 0><<<NN, 64>>>(b4, out_h);        // -> d_out h region

    // ---- Layer 5: 256 -> 5 (no relu) ----
    gemm_small_kernel<<<(NN * 5 + 255) / 256, 256>>>(out_h, Wl5, 0, M, 256, 5);
    gemm_small_kernel<<<(NN * 5 + 255) / 256, 256>>>(out_h, Wr5, 1, M, 256, 5);
    combine5_kernel<<<(NN + 3) / 4, 128>>>(b5, out_cls);
}

// round 11
// speedup vs baseline: 1.4284x; 1.1147x over previous
#include <cuda_runtime.h>
#include <cuda_bf16.h>
#include <cstdint>

#define NN 20000
#define EE 320000

// ================= static scratch =================
__device__ __align__(16) float g_A[NN * 1536];    // GEMM fp32 out (z=0)
__device__ __align__(16) float g_B[NN * 1536];    // GEMM fp32 out (z=1)
// bf16 hi/lo split activation buffers (ping-pong)
__device__ __align__(16) __nv_bfloat16 g_Hh[NN * 1536];
__device__ __align__(16) __nv_bfloat16 g_Hl[NN * 1536];
__device__ __align__(16) __nv_bfloat16 g_H2h[NN * 1536];
__device__ __align__(16) __nv_bfloat16 g_H2l[NN * 1536];
// bf16 transposed-split weights, manual offsets (total 5505024 elems)
__device__ __align__(16) __nv_bfloat16 g_Wh[5505024];
__device__ __align__(16) __nv_bfloat16 g_Wlo[5505024];
__device__ int   g_deg[NN];
__device__ int   g_fill[NN];
__device__ int   g_rowptr[NN + 1];
__device__ int   g_col[EE];
__device__ float g_dinv[NN];

// ================= helpers (baseline PTX, sm_80+) =================
__device__ __forceinline__ uint32_t smem_u32(const void* p) {
    uint32_t a;
    asm("{ .reg .u64 t; cvta.to.shared.u64 t, %1; cvt.u32.u64 %0, t; }" : "=r"(a) : "l"(p));
    return a;
}
__device__ __forceinline__ void ldm_x4(uint32_t* r, uint32_t addr) {
    asm volatile("ldmatrix.sync.aligned.m8n8.x4.shared.b16 {%0,%1,%2,%3}, [%4];"
        : "=r"(r[0]), "=r"(r[1]), "=r"(r[2]), "=r"(r[3]) : "r"(addr));
}
__device__ __forceinline__ void mma16816(float* c, const uint32_t* a, const uint32_t* b) {
    asm volatile("mma.sync.aligned.m16n8k16.row.col.f32.bf16.bf16.f32 "
        "{%0,%1,%2,%3}, {%4,%5,%6,%7}, {%8,%9}, {%0,%1,%2,%3};"
        : "+f"(c[0]), "+f"(c[1]), "+f"(c[2]), "+f"(c[3])
        : "r"(a[0]), "r"(a[1]), "r"(a[2]), "r"(a[3]), "r"(b[0]), "r"(b[1]));
}
__device__ __forceinline__ uint32_t sw128(uint32_t off) {
    return off ^ ((off >> 3) & 0x70);
}
__device__ __forceinline__ uint32_t sw64(uint32_t off) {
    return off ^ ((off >> 3) & 0x30);
}
__device__ __forceinline__ uint32_t pack_bf2(float a, float b) {
    __nv_bfloat162 v = __halves2bfloat162(__float2bfloat16(a), __float2bfloat16(b));
    return *(uint32_t*)&v;
}
#define CP_ASYNC16(saddr, gptr) \
    asm volatile("cp.async.cg.shared.global [%0], [%1], 16;" :: "r"(saddr), "l"(gptr))
#define CP_COMMIT() asm volatile("cp.async.commit_group;")
#define CP_WAIT1()  asm volatile("cp.async.wait_group 1;")

// ================= CSR construction (edge_index int32) =================
__global__ void zero_counts_kernel() {
    int i = blockIdx.x * blockDim.x + threadIdx.x;
    if (i < NN) { g_deg[i] = 0; g_fill[i] = 0; }
}
__global__ void count_deg_kernel(const int* __restrict__ ei) {
    int e = blockIdx.x * blockDim.x + threadIdx.x;
    if (e < EE) {
        int dst = ei[EE + e];
        if ((unsigned)dst < NN) atomicAdd(&g_deg[dst], 1);
    }
}
__global__ void scan_deg_kernel() {
    __shared__ int sh[1024];
    int tid = threadIdx.x;
    int carry = 0;
    if (tid == 0) g_rowptr[0] = 0;
    for (int base = 0; base < NN; base += 1024) {
        int i = base + tid;
        int v = (i < NN) ? g_deg[i] : 0;
        sh[tid] = v;
        __syncthreads();
        for (int off = 1; off < 1024; off <<= 1) {
            int t = (tid >= off) ? sh[tid - off] : 0;
            __syncthreads();
            sh[tid] += t;
            __syncthreads();
        }
        if (i < NN) {
            g_rowptr[i + 1] = carry + sh[tid];
            g_dinv[i] = 1.0f / fmaxf((float)v, 1.0f);
        }
        int last = sh[1023];
        __syncthreads();
        carry += last;
    }
}
__global__ void fill_csr_kernel(const int* __restrict__ ei) {
    int e = blockIdx.x * blockDim.x + threadIdx.x;
    if (e < EE) {
        int src = ei[e];
        int dst = ei[EE + e];
        if ((unsigned)dst < NN && (unsigned)src < NN) {
            int p = atomicAdd(&g_fill[dst], 1);
            g_col[g_rowptr[dst] + p] = src;
        }
    }
}

// ============ weight prep: tiled transpose + bf16 hi/lo split ============
__global__ void wprep_kernel(const float* __restrict__ W, int K, int N,
                             int off, int kofs, int K2) {
    __shared__ float tile[32][33];
    const int k0 = blockIdx.x * 32;
    const int n0 = blockIdx.y * 32;
    const int tx = threadIdx.x, ty = threadIdx.y;   // 32 x 8
#pragma unroll
    for (int r = 0; r < 4; r++)
        tile[ty + r * 8][tx] = W[(size_t)(k0 + ty + r * 8) * N + n0 + tx];
    __syncthreads();
#pragma unroll
    for (int r = 0; r < 4; r++) {
        int n = n0 + ty + r * 8;
        float w = tile[tx][ty + r * 8];
        __nv_bfloat16 hi = __float2bfloat16(w);
        size_t d = (size_t)off + (size_t)n * K2 + kofs + k0 + tx;
        g_Wh[d] = hi;
        g_Wlo[d] = __float2bfloat16(w - __bfloat162float(hi));
    }
}

// fused: mean-aggregate neighbors -> split -> cols [0,768);
//        split own x row -> cols [768,1536). Block per node, 192 threads.
__global__ __launch_bounds__(192) void prep_x_kernel(const float* __restrict__ x) {
    const int node = blockIdx.x;
    const int tid = threadIdx.x;
    const int s = g_rowptr[node];
    const int e = g_rowptr[node + 1];
    float4 acc = make_float4(0.f, 0.f, 0.f, 0.f);
    __shared__ int nb[192];
    for (int base = s; base < e; base += 192) {
        int cnt = min(192, e - base);
        if (tid < cnt) nb[tid] = g_col[base + tid];
        __syncthreads();
        for (int j = 0; j < cnt; j++) {
            float4 v = ((const float4*)(x + (size_t)nb[j] * 768))[tid];
            acc.x += v.x; acc.y += v.y; acc.z += v.z; acc.w += v.w;
        }
        __syncthreads();
    }
    const float di = g_dinv[node];
    acc.x *= di; acc.y *= di; acc.z *= di; acc.w *= di;
    {
        float hx = __bfloat162float(__float2bfloat16(acc.x));
        float hy = __bfloat162float(__float2bfloat16(acc.y));
        float hz = __bfloat162float(__float2bfloat16(acc.z));
        float hw = __bfloat162float(__float2bfloat16(acc.w));
        size_t d = (size_t)node * 1536 + tid * 4;
        *(uint2*)(g_Hh + d) = make_uint2(pack_bf2(acc.x, acc.y), pack_bf2(acc.z, acc.w));
        *(uint2*)(g_Hl + d) = make_uint2(pack_bf2(acc.x - hx, acc.y - hy), pack_bf2(acc.z - hz, acc.w - hw));
    }
    {
        float4 v = ((const float4*)(x + (size_t)node * 768))[tid];
        float hx = __bfloat162float(__float2bfloat16(v.x));
        float hy = __bfloat162float(__float2bfloat16(v.y));
        float hz = __bfloat162float(__float2bfloat16(v.z));
        float hw = __bfloat162float(__float2bfloat16(v.w));
        size_t d = (size_t)node * 1536 + 768 + tid * 4;
        *(uint2*)(g_Hh + d) = make_uint2(pack_bf2(v.x, v.y), pack_bf2(v.z, v.w));
        *(uint2*)(g_Hl + d) = make_uint2(pack_bf2(v.x - hx, v.y - hy), pack_bf2(v.z - hz, v.w - hw));
    }
}

// ======= HMMA GEMM: BM=128, BN=128, BK=32, 3-stage, 2 CTAs/SM =======
// AB: 0 -> A from g_Hh/g_Hl, 1 -> A from g_H2h/g_H2l
// EPI: 0 -> fp32 out to (z ? g_B : g_A); gridDim.z = 2, weights woff_l/woff_r
// EPI: 1 -> fused bias+relu+split out to the OTHER buffer pair; gridDim.z = 1
// stage: Ah(8K)|Al(8K)|Bh(8K)|Bl(8K) = 32KB; rows 64B wide, SW64 swizzle.
#define STG 32768
#define NSTAGE 3
template <int AB, int EPI>
__global__ __launch_bounds__(256, 2) void bgemm_kernel(
    int woff_l, int woff_r, const float* __restrict__ bias,
    int M, int Kd, int Nd)
{
    extern __shared__ __align__(1024) uint8_t dsm[];
    const __nv_bfloat16* Ah = AB ? g_H2h : g_Hh;
    const __nv_bfloat16* Al = AB ? g_H2l : g_Hl;
    const int tid = threadIdx.x;
    const int wid = tid >> 5;
    const int lane = tid & 31;
    const int m0 = blockIdx.y * 128;
    const int n0 = blockIdx.x * 128;
    const int woff = blockIdx.z ? woff_r : woff_l;
    const int warp_m = (wid & 1) * 64;
    const int warp_n = (wid >> 1) * 32;
    const uint32_t sb = smem_u32(dsm);

    // loads: 2 threads/row; q selects 32B half of the 64B row
    const int lrow = tid >> 1;
    const int q = tid & 1;
    const int arow = min(m0 + lrow, M - 1);
    const __nv_bfloat16* gAh = Ah + (size_t)arow * Kd + q * 16;
    const __nv_bfloat16* gAl = Al + (size_t)arow * Kd + q * 16;
    const __nv_bfloat16* gBh = g_Wh + woff + (size_t)(n0 + lrow) * Kd + q * 16;
    const __nv_bfloat16* gBl = g_Wlo + woff + (size_t)(n0 + lrow) * Kd + q * 16;
    const uint32_t dbase = lrow * 64 + q * 32;

    float acc[4][4][4];
#pragma unroll
    for (int mi = 0; mi < 4; mi++)
#pragma unroll
        for (int ni = 0; ni < 4; ni++)
#pragma unroll
            for (int qq = 0; qq < 4; qq++) acc[mi][ni][qq] = 0.f;

    const int sub = lane >> 3;
    const int lr = lane & 7;
    const int nch = Kd >> 5;

#define ISSUE32(stadr, kofs) do { \
        uint32_t _sa = (stadr); \
        _Pragma("unroll") \
        for (int j = 0; j < 2; j++) { \
            uint32_t o = sw64(dbase + j * 16); \
            CP_ASYNC16(_sa + o,         gAh + (kofs) + j * 8); \
            CP_ASYNC16(_sa + 8192 + o,  gAl + (kofs) + j * 8); \
            CP_ASYNC16(_sa + 16384 + o, gBh + (kofs) + j * 8); \
            CP_ASYNC16(_sa + 24576 + o, gBl + (kofs) + j * 8); \
        } \
    } while (0)

    // prologue: chunks 0 and 1
    ISSUE32(sb, 0);
    CP_COMMIT();
    if (1 < nch) ISSUE32(sb + STG, 32);
    CP_COMMIT();

    int st = 0;
    int st2 = 2;
    for (int ch = 0; ch < nch; ch++) {
        CP_WAIT1();
        __syncthreads();

        if (ch + 2 < nch) ISSUE32(sb + st2 * STG, (ch + 2) << 5);
        CP_COMMIT();

        const uint32_t sAh = sb + st * STG;
        const uint32_t sAl = sAh + 8192;
        const uint32_t sBh = sAh + 16384;
        const uint32_t sBl = sAh + 24576;

#pragma unroll
        for (int ks = 0; ks < 2; ks++) {
            uint32_t bh[2][4], bl[2][4];
#pragma unroll
            for (int np = 0; np < 2; np++) {
                int row = warp_n + np * 16 + (sub >> 1) * 8 + lr;
                uint32_t kb = ks * 32 + (sub & 1) * 16;
                uint32_t o = sw64(row * 64 + kb);
                ldm_x4(bh[np], sBh + o);
                ldm_x4(bl[np], sBl + o);
            }
#pragma unroll
            for (int mi = 0; mi < 4; mi++) {
                uint32_t ah[4], al[4];
                int row = warp_m + mi * 16 + (sub & 1) * 8 + lr;
                uint32_t kb = ks * 32 + (sub >> 1) * 16;
                uint32_t o = sw64(row * 64 + kb);
                ldm_x4(ah, sAh + o);
                ldm_x4(al, sAl + o);
#pragma unroll
                for (int ni = 0; ni < 4; ni++) {
                    const uint32_t* ph = &bh[ni >> 1][(ni & 1) * 2];
                    const uint32_t* pl = &bl[ni >> 1][(ni & 1) * 2];
                    mma16816(acc[mi][ni], ah, ph);
                    mma16816(acc[mi][ni], ah, pl);
                    mma16816(acc[mi][ni], al, ph);
                }
            }
        }
        st = (st == 2) ? 0 : st + 1;
        st2 = (st2 == 2) ? 0 : st2 + 1;
    }

    // ---- epilogue ----
    const int g = lane >> 2;
    const int t = lane & 3;
    if constexpr (EPI == 0) {
        float* C = blockIdx.z ? g_B : g_A;
#pragma unroll
        for (int mi = 0; mi < 4; mi++) {
            int r0 = m0 + warp_m + mi * 16 + g;
            int r1 = r0 + 8;
#pragma unroll
            for (int ni = 0; ni < 4; ni++) {
                int col = n0 + warp_n + ni * 8 + t * 2;
                if (r0 < M) *(float2*)(C + (size_t)r0 * Nd + col) = make_float2(acc[mi][ni][0], acc[mi][ni][1]);
                if (r1 < M) *(float2*)(C + (size_t)r1 * Nd + col) = make_float2(acc[mi][ni][2], acc[mi][ni][3]);
            }
        }
    } else {
        __nv_bfloat16* Oh = AB ? g_Hh : g_H2h;
        __nv_bfloat16* Ol = AB ? g_Hl : g_H2l;
#pragma unroll
        for (int mi = 0; mi < 4; mi++) {
            int r0 = m0 + warp_m + mi * 16 + g;
            int r1 = r0 + 8;
#pragma unroll
            for (int ni = 0; ni < 4; ni++) {
                int col = n0 + warp_n + ni * 8 + t * 2;
                float b0 = bias[col], b1v = bias[col + 1];
                float v0 = fmaxf(acc[mi][ni][0] + b0, 0.f);
                float v1 = fmaxf(acc[mi][ni][1] + b1v, 0.f);
                float v2 = fmaxf(acc[mi][ni][2] + b0, 0.f);
                float v3 = fmaxf(acc[mi][ni][3] + b1v, 0.f);
                float h0 = __bfloat162float(__float2bfloat16(v0));
                float h1 = __bfloat162float(__float2bfloat16(v1));
                float h2 = __bfloat162float(__float2bfloat16(v2));
                float h3 = __bfloat162float(__float2bfloat16(v3));
                if (r0 < M) {
                    *(uint32_t*)(Oh + (size_t)r0 * Nd + col) = pack_bf2(v0, v1);
                    *(uint32_t*)(Ol + (size_t)r0 * Nd + col) = pack_bf2(v0 - h0, v1 - h1);
                }
                if (r1 < M) {
                    *(uint32_t*)(Oh + (size_t)r1 * Nd + col) = pack_bf2(v2, v3);
                    *(uint32_t*)(Ol + (size_t)r1 * Nd + col) = pack_bf2(v2 - h2, v3 - h3);
                }
            }
        }
    }
}

// ================= small-N GEMM for the final 256->5 linear =================
// blockIdx.y selects Wl (0 -> g_A) or Wr (1 -> g_B)
__global__ void gemm_small_kernel(const float* __restrict__ Aext,
                                  const float* __restrict__ W0,
                                  const float* __restrict__ W1,
                                  int M, int Kd, int Nd)
{
    const float* W = blockIdx.y ? W1 : W0;
    float* C = blockIdx.y ? g_B : g_A;
    int idx = blockIdx.x * blockDim.x + threadIdx.x;
    if (idx >= M * Nd) return;
    int row = idx / Nd, c = idx % Nd;
    const float* a = Aext + (size_t)row * Kd;
    float acc = 0.f;
    for (int k = 0; k < Kd; k++) acc += a[k] * W[k * Nd + c];
    C[idx] = acc;
}

// ================= combine (layers 2-4): r = relu(di*agg(g_A) + g_B + b) ===
template <int F, int OM>
__global__ void combine_kernel(const float* __restrict__ bias,
                               float* __restrict__ outExt)
{
    constexpr int NT = F / 4;
    const int node = blockIdx.x;
    const int tid = threadIdx.x;
    const int s = g_rowptr[node];
    const int e = g_rowptr[node + 1];

    float4 acc = make_float4(0.f, 0.f, 0.f, 0.f);
    __shared__ int nb[NT];
    for (int base = s; base < e; base += NT) {
        int cnt = min(NT, e - base);
        if (tid < cnt) nb[tid] = g_col[base + tid];
        __syncthreads();
        for (int j = 0; j < cnt; j++) {
            float4 v = ((const float4*)(g_A + (size_t)nb[j] * F))[tid];
            acc.x += v.x; acc.y += v.y; acc.z += v.z; acc.w += v.w;
        }
        __syncthreads();
    }

    const float di = g_dinv[node];
    float4 sv = ((const float4*)(g_B + (size_t)node * F))[tid];
    float4 bv = ((const float4*)bias)[tid];
    float rx = fmaxf(acc.x * di + sv.x + bv.x, 0.f);
    float ry = fmaxf(acc.y * di + sv.y + bv.y, 0.f);
    float rz = fmaxf(acc.z * di + sv.z + bv.z, 0.f);
    float rw = fmaxf(acc.w * di + sv.w + bv.w, 0.f);

    if constexpr (OM == 0) {
        ((float4*)(outExt + (size_t)node * F))[tid] = make_float4(rx, ry, rz, rw);
    } else {
        __nv_bfloat16* Oh = (OM == 1) ? g_Hh : g_H2h;
        __nv_bfloat16* Ol = (OM == 1) ? g_Hl : g_H2l;
        float hx = __bfloat162float(__float2bfloat16(rx));
        float hy = __bfloat162float(__float2bfloat16(ry));
        float hz = __bfloat162float(__float2bfloat16(rz));
        float hw = __bfloat162float(__float2bfloat16(rw));
        size_t d = (size_t)node * F + tid * 4;
        *(uint2*)(Oh + d) = make_uint2(pack_bf2(rx, ry), pack_bf2(rz, rw));
        *(uint2*)(Ol + d) = make_uint2(pack_bf2(rx - hx, ry - hy), pack_bf2(rz - hz, rw - hw));
    }
}

__global__ void combine5_kernel(const float* __restrict__ bias,
                                float* __restrict__ out)
{
    int node = blockIdx.x * 4 + (threadIdx.x >> 5);
    if (node >= NN) return;
    int lane = threadIdx.x & 31;
    if (lane >= 5) return;
    int s = g_rowptr[node], e = g_rowptr[node + 1];
    float acc = 0.f;
    for (int j = s; j < e; j++) acc += g_A[g_col[j] * 5 + lane];
    out[node * 5 + lane] = acc * g_dinv[node] + g_B[node * 5 + lane] + bias[lane];
}

// ================= launch =================
extern "C" void kernel_launch(void* const* d_in, const int* in_sizes, int n_in,
                              void* d_out, int out_size)
{
    const float* x  = (const float*)d_in[0];
    const int*   ei = (const int*)d_in[1];
    const float* Wl1 = (const float*)d_in[2];
    const float* Wr1 = (const float*)d_in[3];
    const float* b1  = (const float*)d_in[4];
    const float* Wl2 = (const float*)d_in[5];
    const float* Wr2 = (const float*)d_in[6];
    const float* b2  = (const float*)d_in[7];
    const float* Wl3 = (const float*)d_in[8];
    const float* Wr3 = (const float*)d_in[9];
    const float* b3  = (const float*)d_in[10];
    const float* Wl4 = (const float*)d_in[11];
    const float* Wr4 = (const float*)d_in[12];
    const float* b4  = (const float*)d_in[13];
    const float* Wl5 = (const float*)d_in[14];
    const float* Wr5 = (const float*)d_in[15];
    const float* b5  = (const float*)d_in[16];

    float* out = (float*)d_out;
    float* out_h   = out;                      // [NN, 256]
    float* out_cls = out + (size_t)NN * 256;   // [NN, 5]

    const int SMEM_SZ = NSTAGE * STG;   // 96 KB -> 2 CTAs/SM
    cudaFuncSetAttribute(bgemm_kernel<0, 1>, cudaFuncAttributeMaxDynamicSharedMemorySize, SMEM_SZ);
    cudaFuncSetAttribute(bgemm_kernel<1, 0>, cudaFuncAttributeMaxDynamicSharedMemorySize, SMEM_SZ);
    cudaFuncSetAttribute(bgemm_kernel<0, 0>, cudaFuncAttributeMaxDynamicSharedMemorySize, SMEM_SZ);

    // ---- CSR build ----
    zero_counts_kernel<<<(NN + 255) / 256, 256>>>();
    count_deg_kernel<<<(EE + 255) / 256, 256>>>(ei);
    scan_deg_kernel<<<1, 1024>>>();
    fill_csr_kernel<<<(EE + 255) / 256, 256>>>(ei);

    // ---- weight prep (tiled transpose + split) ----
    const int OFF1 = 0;
    const int OFF2L = 2359296, OFF2R = 3538944;
    const int OFF3L = 4718592, OFF3R = 5013504;
    const int OFF4L = 5308416, OFF4R = 5406720;
    dim3 tb(32, 8);
    wprep_kernel<<<dim3(768 / 32, 1536 / 32), tb>>>(Wl1, 768, 1536, OFF1, 0, 1536);
    wprep_kernel<<<dim3(768 / 32, 1536 / 32), tb>>>(Wr1, 768, 1536, OFF1, 768, 1536);
    wprep_kernel<<<dim3(1536 / 32, 768 / 32), tb>>>(Wl2, 1536, 768, OFF2L, 0, 1536);
    wprep_kernel<<<dim3(1536 / 32, 768 / 32), tb>>>(Wr2, 1536, 768, OFF2R, 0, 1536);
    wprep_kernel<<<dim3(768 / 32, 384 / 32), tb>>>(Wl3, 768, 384, OFF3L, 0, 768);
    wprep_kernel<<<dim3(768 / 32, 384 / 32), tb>>>(Wr3, 768, 384, OFF3R, 0, 768);
    wprep_kernel<<<dim3(384 / 32, 256 / 32), tb>>>(Wl4, 384, 256, OFF4L, 0, 384);
    wprep_kernel<<<dim3(384 / 32, 256 / 32), tb>>>(Wr4, 384, 256, OFF4R, 0, 384);

    // ---- input prep: fused agg + self split ----
    prep_x_kernel<<<NN, 192>>>(x);

    const int M = NN;
    const int gy = (M + 127) / 128;   // 157

    // ---- Layer 1: fused [agg|x] @ [[Wl],[Wr]] (K=1536) + bias+relu+split ----
    bgemm_kernel<0, 1><<<dim3(12, gy, 1), 256, SMEM_SZ>>>(OFF1, OFF1, b1, M, 1536, 1536);  // -> buf1

    // ---- Layer 2: 1536 -> 768 ----
    bgemm_kernel<1, 0><<<dim3(6, gy, 2), 256, SMEM_SZ>>>(OFF2L, OFF2R, nullptr, M, 1536, 768);
    combine_kernel<768, 1><<<NN, 192>>>(b2, nullptr);     // -> buf0

    // ---- Layer 3: 768 -> 384 ----
    bgemm_kernel<0, 0><<<dim3(3, gy, 2), 256, SMEM_SZ>>>(OFF3L, OFF3R, nullptr, M, 768, 384);
    combine_kernel<384, 2><<<NN, 96>>>(b3, nullptr);      // -> buf1

    // ---- Layer 4: 384 -> 256 (h output fp32) ----
    bgemm_kernel<1, 0><<<dim3(2, gy, 2), 256, SMEM_SZ>>>(OFF4L, OFF4R, nullptr, M, 384, 256);
    combine_kernel<256, 0><<<NN, 64>>>(b4, out_h);        // -> d_out h region

    // ---- Layer 5: 256 -> 5 (no relu) ----
    gemm_small_kernel<<<dim3((NN * 5 + 255) / 256, 2), 256>>>(out_h, Wl5, Wr5, M, 256, 5);
    combine5_kernel<<<(NN + 3) / 4, 128>>>(b5, out_cls);
}

// round 12
// speedup vs baseline: 1.4406x; 1.0086x over previous
#include <cuda_runtime.h>
#include <cuda_bf16.h>
#include <cstdint>

#define NN 20000
#define EE 320000

// ================= static scratch =================
__device__ __align__(16) float g_A[NN * 1536];    // GEMM fp32 out (z=0)
__device__ __align__(16) float g_B[NN * 1536];    // GEMM fp32 out (z=1)
// bf16 hi/lo split activation buffers (ping-pong)
__device__ __align__(16) __nv_bfloat16 g_Hh[NN * 1536];
__device__ __align__(16) __nv_bfloat16 g_Hl[NN * 1536];
__device__ __align__(16) __nv_bfloat16 g_H2h[NN * 1536];
__device__ __align__(16) __nv_bfloat16 g_H2l[NN * 1536];
// bf16 transposed-split weights, manual offsets (total 5505024 elems)
__device__ __align__(16) __nv_bfloat16 g_Wh[5505024];
__device__ __align__(16) __nv_bfloat16 g_Wlo[5505024];
__device__ int   g_deg[NN];
__device__ int   g_fill[NN];
__device__ int   g_rowptr[NN + 1];
__device__ int   g_col[EE];
__device__ float g_dinv[NN];

// ================= helpers (baseline PTX, sm_80+) =================
__device__ __forceinline__ uint32_t smem_u32(const void* p) {
    uint32_t a;
    asm("{ .reg .u64 t; cvta.to.shared.u64 t, %1; cvt.u32.u64 %0, t; }" : "=r"(a) : "l"(p));
    return a;
}
__device__ __forceinline__ void ldm_x4(uint32_t* r, uint32_t addr) {
    asm volatile("ldmatrix.sync.aligned.m8n8.x4.shared.b16 {%0,%1,%2,%3}, [%4];"
        : "=r"(r[0]), "=r"(r[1]), "=r"(r[2]), "=r"(r[3]) : "r"(addr));
}
__device__ __forceinline__ void mma16816(float* c, const uint32_t* a, const uint32_t* b) {
    asm volatile("mma.sync.aligned.m16n8k16.row.col.f32.bf16.bf16.f32 "
        "{%0,%1,%2,%3}, {%4,%5,%6,%7}, {%8,%9}, {%0,%1,%2,%3};"
        : "+f"(c[0]), "+f"(c[1]), "+f"(c[2]), "+f"(c[3])
        : "r"(a[0]), "r"(a[1]), "r"(a[2]), "r"(a[3]), "r"(b[0]), "r"(b[1]));
}
__device__ __forceinline__ uint32_t sw64(uint32_t off) {
    return off ^ ((off >> 3) & 0x30);
}
__device__ __forceinline__ uint32_t pack_bf2(float a, float b) {
    __nv_bfloat162 v = __halves2bfloat162(__float2bfloat16(a), __float2bfloat16(b));
    return *(uint32_t*)&v;
}
#define CP_ASYNC16(saddr, gptr) \
    asm volatile("cp.async.cg.shared.global [%0], [%1], 16;" :: "r"(saddr), "l"(gptr))
#define CP_COMMIT() asm volatile("cp.async.commit_group;")
#define CP_WAIT1()  asm volatile("cp.async.wait_group 1;")

// ================= CSR construction (edge_index int32) =================
__global__ void zero_counts_kernel() {
    int i = blockIdx.x * blockDim.x + threadIdx.x;
    if (i < NN) { g_deg[i] = 0; g_fill[i] = 0; }
}
__global__ void count_deg_kernel(const int* __restrict__ ei) {
    int e = blockIdx.x * blockDim.x + threadIdx.x;
    if (e < EE) {
        int dst = ei[EE + e];
        if ((unsigned)dst < NN) atomicAdd(&g_deg[dst], 1);
    }
}
// shuffle-based single-block scan: 1024 threads x 20 elems each
__global__ __launch_bounds__(1024) void scan_deg_kernel() {
    const int PER = 20;
    const int tid = threadIdx.x;
    const int lane = tid & 31;
    const int warp = tid >> 5;
    const int base = tid * PER;

    int incl[PER];
    int s = 0;
#pragma unroll
    for (int i = 0; i < PER; i++) {
        int idx = base + i;
        int v = (idx < NN) ? g_deg[idx] : 0;
        s += v;
        incl[i] = s;
    }
    // warp inclusive scan of per-thread totals
    int ssum = s;
#pragma unroll
    for (int off = 1; off < 32; off <<= 1) {
        int t = __shfl_up_sync(0xffffffffu, ssum, off);
        if (lane >= off) ssum += t;
    }
    __shared__ int wsum[32];
    if (lane == 31) wsum[warp] = ssum;
    __syncthreads();
    if (warp == 0) {
        int w = wsum[lane];
#pragma unroll
        for (int off = 1; off < 32; off <<= 1) {
            int t = __shfl_up_sync(0xffffffffu, w, off);
            if (lane >= off) w += t;
        }
        wsum[lane] = w;
    }
    __syncthreads();
    const int offset = (warp ? wsum[warp - 1] : 0) + (ssum - s);   // exclusive prefix
    if (tid == 0) g_rowptr[0] = 0;
#pragma unroll
    for (int i = 0; i < PER; i++) {
        int idx = base + i;
        if (idx < NN) {
            g_rowptr[idx + 1] = offset + incl[i];
            int d = incl[i] - (i ? incl[i - 1] : 0);
            g_dinv[idx] = 1.0f / fmaxf((float)d, 1.0f);
        }
    }
}
__global__ void fill_csr_kernel(const int* __restrict__ ei) {
    int e = blockIdx.x * blockDim.x + threadIdx.x;
    if (e < EE) {
        int src = ei[e];
        int dst = ei[EE + e];
        if ((unsigned)dst < NN && (unsigned)src < NN) {
            int p = atomicAdd(&g_fill[dst], 1);
            g_col[g_rowptr[dst] + p] = src;
        }
    }
}

// ============ merged weight prep: 8 matrices, one launch ============
struct WDescs {
    const float* W[8];
    int K[8], N[8], off[8], kofs[8], K2[8], tstart[8], tilesX[8];
};
__global__ void wprep_all_kernel(WDescs d) {
    __shared__ float tile[32][33];
    const int bid = blockIdx.x;
    int m = 0;
#pragma unroll
    for (int i = 1; i < 8; i++)
        if (bid >= d.tstart[i]) m = i;
    const int lt = bid - d.tstart[m];
    const int k0 = (lt % d.tilesX[m]) * 32;
    const int n0 = (lt / d.tilesX[m]) * 32;
    const float* W = d.W[m];
    const int K = d.K[m], N = d.N[m], off = d.off[m], kofs = d.kofs[m], K2 = d.K2[m];
    const int tx = threadIdx.x, ty = threadIdx.y;   // 32 x 8
#pragma unroll
    for (int r = 0; r < 4; r++)
        tile[ty + r * 8][tx] = W[(size_t)(k0 + ty + r * 8) * N + n0 + tx];
    __syncthreads();
#pragma unroll
    for (int r = 0; r < 4; r++) {
        int n = n0 + ty + r * 8;
        float w = tile[tx][ty + r * 8];
        __nv_bfloat16 hi = __float2bfloat16(w);
        size_t dd = (size_t)off + (size_t)n * K2 + kofs + k0 + tx;
        g_Wh[dd] = hi;
        g_Wlo[dd] = __float2bfloat16(w - __bfloat162float(hi));
    }
    (void)K;
}

// fused: mean-aggregate neighbors -> split -> cols [0,768);
//        split own x row -> cols [768,1536). Block per node, 192 threads.
__global__ __launch_bounds__(192) void prep_x_kernel(const float* __restrict__ x) {
    const int node = blockIdx.x;
    const int tid = threadIdx.x;
    const int s = g_rowptr[node];
    const int e = g_rowptr[node + 1];
    float4 acc = make_float4(0.f, 0.f, 0.f, 0.f);
    __shared__ int nb[192];
    for (int base = s; base < e; base += 192) {
        int cnt = min(192, e - base);
        if (tid < cnt) nb[tid] = g_col[base + tid];
        __syncthreads();
        for (int j = 0; j < cnt; j++) {
            float4 v = ((const float4*)(x + (size_t)nb[j] * 768))[tid];
            acc.x += v.x; acc.y += v.y; acc.z += v.z; acc.w += v.w;
        }
        __syncthreads();
    }
    const float di = g_dinv[node];
    acc.x *= di; acc.y *= di; acc.z *= di; acc.w *= di;
    {
        float hx = __bfloat162float(__float2bfloat16(acc.x));
        float hy = __bfloat162float(__float2bfloat16(acc.y));
        float hz = __bfloat162float(__float2bfloat16(acc.z));
        float hw = __bfloat162float(__float2bfloat16(acc.w));
        size_t d = (size_t)node * 1536 + tid * 4;
        *(uint2*)(g_Hh + d) = make_uint2(pack_bf2(acc.x, acc.y), pack_bf2(acc.z, acc.w));
        *(uint2*)(g_Hl + d) = make_uint2(pack_bf2(acc.x - hx, acc.y - hy), pack_bf2(acc.z - hz, acc.w - hw));
    }
    {
        float4 v = ((const float4*)(x + (size_t)node * 768))[tid];
        float hx = __bfloat162float(__float2bfloat16(v.x));
        float hy = __bfloat162float(__float2bfloat16(v.y));
        float hz = __bfloat162float(__float2bfloat16(v.z));
        float hw = __bfloat162float(__float2bfloat16(v.w));
        size_t d = (size_t)node * 1536 + 768 + tid * 4;
        *(uint2*)(g_Hh + d) = make_uint2(pack_bf2(v.x, v.y), pack_bf2(v.z, v.w));
        *(uint2*)(g_Hl + d) = make_uint2(pack_bf2(v.x - hx, v.y - hy), pack_bf2(v.z - hz, v.w - hw));
    }
}

// ======= HMMA GEMM: BM=128, BN=128, BK=32, 3-stage, 2 CTAs/SM =======
#define STG 32768
#define NSTAGE 3
template <int AB, int EPI>
__global__ __launch_bounds__(256, 2) void bgemm_kernel(
    int woff_l, int woff_r, const float* __restrict__ bias,
    int M, int Kd, int Nd)
{
    extern __shared__ __align__(1024) uint8_t dsm[];
    const __nv_bfloat16* Ah = AB ? g_H2h : g_Hh;
    const __nv_bfloat16* Al = AB ? g_H2l : g_Hl;
    const int tid = threadIdx.x;
    const int wid = tid >> 5;
    const int lane = tid & 31;
    const int m0 = blockIdx.y * 128;
    const int n0 = blockIdx.x * 128;
    const int woff = blockIdx.z ? woff_r : woff_l;
    const int warp_m = (wid & 1) * 64;
    const int warp_n = (wid >> 1) * 32;
    const uint32_t sb = smem_u32(dsm);

    const int lrow = tid >> 1;
    const int q = tid & 1;
    const int arow = min(m0 + lrow, M - 1);
    const __nv_bfloat16* gAh = Ah + (size_t)arow * Kd + q * 16;
    const __nv_bfloat16* gAl = Al + (size_t)arow * Kd + q * 16;
    const __nv_bfloat16* gBh = g_Wh + woff + (size_t)(n0 + lrow) * Kd + q * 16;
    const __nv_bfloat16* gBl = g_Wlo + woff + (size_t)(n0 + lrow) * Kd + q * 16;
    const uint32_t dbase = lrow * 64 + q * 32;

    float acc[4][4][4];
#pragma unroll
    for (int mi = 0; mi < 4; mi++)
#pragma unroll
        for (int ni = 0; ni < 4; ni++)
#pragma unroll
            for (int qq = 0; qq < 4; qq++) acc[mi][ni][qq] = 0.f;

    const int sub = lane >> 3;
    const int lr = lane & 7;
    const int nch = Kd >> 5;

#define ISSUE32(stadr, kofs) do { \
        uint32_t _sa = (stadr); \
        _Pragma("unroll") \
        for (int j = 0; j < 2; j++) { \
            uint32_t o = sw64(dbase + j * 16); \
            CP_ASYNC16(_sa + o,         gAh + (kofs) + j * 8); \
            CP_ASYNC16(_sa + 8192 + o,  gAl + (kofs) + j * 8); \
            CP_ASYNC16(_sa + 16384 + o, gBh + (kofs) + j * 8); \
            CP_ASYNC16(_sa + 24576 + o, gBl + (kofs) + j * 8); \
        } \
    } while (0)

    ISSUE32(sb, 0);
    CP_COMMIT();
    if (1 < nch) ISSUE32(sb + STG, 32);
    CP_COMMIT();

    int st = 0;
    int st2 = 2;
    for (int ch = 0; ch < nch; ch++) {
        CP_WAIT1();
        __syncthreads();

        if (ch + 2 < nch) ISSUE32(sb + st2 * STG, (ch + 2) << 5);
        CP_COMMIT();

        const uint32_t sAh = sb + st * STG;
        const uint32_t sAl = sAh + 8192;
        const uint32_t sBh = sAh + 16384;
        const uint32_t sBl = sAh + 24576;

#pragma unroll
        for (int ks = 0; ks < 2; ks++) {
            uint32_t bh[2][4], bl[2][4];
#pragma unroll
            for (int np = 0; np < 2; np++) {
                int row = warp_n + np * 16 + (sub >> 1) * 8 + lr;
                uint32_t kb = ks * 32 + (sub & 1) * 16;
                uint32_t o = sw64(row * 64 + kb);
                ldm_x4(bh[np], sBh + o);
                ldm_x4(bl[np], sBl + o);
            }
#pragma unroll
            for (int mi = 0; mi < 4; mi++) {
                uint32_t ah[4], al[4];
                int row = warp_m + mi * 16 + (sub & 1) * 8 + lr;
                uint32_t kb = ks * 32 + (sub >> 1) * 16;
                uint32_t o = sw64(row * 64 + kb);
                ldm_x4(ah, sAh + o);
                ldm_x4(al, sAl + o);
#pragma unroll
                for (int ni = 0; ni < 4; ni++) {
                    const uint32_t* ph = &bh[ni >> 1][(ni & 1) * 2];
                    const uint32_t* pl = &bl[ni >> 1][(ni & 1) * 2];
                    mma16816(acc[mi][ni], ah, ph);
                    mma16816(acc[mi][ni], ah, pl);
                    mma16816(acc[mi][ni], al, ph);
                }
            }
        }
        st = (st == 2) ? 0 : st + 1;
        st2 = (st2 == 2) ? 0 : st2 + 1;
    }

    // ---- epilogue ----
    const int g = lane >> 2;
    const int t = lane & 3;
    if constexpr (EPI == 0) {
        float* C = blockIdx.z ? g_B : g_A;
#pragma unroll
        for (int mi = 0; mi < 4; mi++) {
            int r0 = m0 + warp_m + mi * 16 + g;
            int r1 = r0 + 8;
#pragma unroll
            for (int ni = 0; ni < 4; ni++) {
                int col = n0 + warp_n + ni * 8 + t * 2;
                if (r0 < M) *(float2*)(C + (size_t)r0 * Nd + col) = make_float2(acc[mi][ni][0], acc[mi][ni][1]);
                if (r1 < M) *(float2*)(C + (size_t)r1 * Nd + col) = make_float2(acc[mi][ni][2], acc[mi][ni][3]);
            }
        }
    } else {
        __nv_bfloat16* Oh = AB ? g_Hh : g_H2h;
        __nv_bfloat16* Ol = AB ? g_Hl : g_H2l;
#pragma unroll
        for (int mi = 0; mi < 4; mi++) {
            int r0 = m0 + warp_m + mi * 16 + g;
            int r1 = r0 + 8;
#pragma unroll
            for (int ni = 0; ni < 4; ni++) {
                int col = n0 + warp_n + ni * 8 + t * 2;
                float b0 = bias[col], b1v = bias[col + 1];
                float v0 = fmaxf(acc[mi][ni][0] + b0, 0.f);
                float v1 = fmaxf(acc[mi][ni][1] + b1v, 0.f);
                float v2 = fmaxf(acc[mi][ni][2] + b0, 0.f);
                float v3 = fmaxf(acc[mi][ni][3] + b1v, 0.f);
                float h0 = __bfloat162float(__float2bfloat16(v0));
                float h1 = __bfloat162float(__float2bfloat16(v1));
                float h2 = __bfloat162float(__float2bfloat16(v2));
                float h3 = __bfloat162float(__float2bfloat16(v3));
                if (r0 < M) {
                    *(uint32_t*)(Oh + (size_t)r0 * Nd + col) = pack_bf2(v0, v1);
                    *(uint32_t*)(Ol + (size_t)r0 * Nd + col) = pack_bf2(v0 - h0, v1 - h1);
                }
                if (r1 < M) {
                    *(uint32_t*)(Oh + (size_t)r1 * Nd + col) = pack_bf2(v2, v3);
                    *(uint32_t*)(Ol + (size_t)r1 * Nd + col) = pack_bf2(v2 - h2, v3 - h3);
                }
            }
        }
    }
}

// ================= small-N GEMM for the final 256->5 linear =================
__global__ void gemm_small_kernel(const float* __restrict__ Aext,
                                  const float* __restrict__ W0,
                                  const float* __restrict__ W1,
                                  int M, int Kd, int Nd)
{
    const float* W = blockIdx.y ? W1 : W0;
    float* C = blockIdx.y ? g_B : g_A;
    int idx = blockIdx.x * blockDim.x + threadIdx.x;
    if (idx >= M * Nd) return;
    int row = idx / Nd, c = idx % Nd;
    const float* a = Aext + (size_t)row * Kd;
    float acc = 0.f;
    for (int k = 0; k < Kd; k++) acc += a[k] * W[k * Nd + c];
    C[idx] = acc;
}

// ================= combine (layers 2-4): r = relu(di*agg(g_A) + g_B + b) ===
template <int F, int OM>
__global__ void combine_kernel(const float* __restrict__ bias,
                               float* __restrict__ outExt)
{
    constexpr int NT = F / 4;
    const int node = blockIdx.x;
    const int tid = threadIdx.x;
    const int s = g_rowptr[node];
    const int e = g_rowptr[node + 1];

    float4 acc = make_float4(0.f, 0.f, 0.f, 0.f);
    __shared__ int nb[NT];
    for (int base = s; base < e; base += NT) {
        int cnt = min(NT, e - base);
        if (tid < cnt) nb[tid] = g_col[base + tid];
        __syncthreads();
        for (int j = 0; j < cnt; j++) {
            float4 v = ((const float4*)(g_A + (size_t)nb[j] * F))[tid];
            acc.x += v.x; acc.y += v.y; acc.z += v.z; acc.w += v.w;
        }
        __syncthreads();
    }

    const float di = g_dinv[node];
    float4 sv = ((const float4*)(g_B + (size_t)node * F))[tid];
    float4 bv = ((const float4*)bias)[tid];
    float rx = fmaxf(acc.x * di + sv.x + bv.x, 0.f);
    float ry = fmaxf(acc.y * di + sv.y + bv.y, 0.f);
    float rz = fmaxf(acc.z * di + sv.z + bv.z, 0.f);
    float rw = fmaxf(acc.w * di + sv.w + bv.w, 0.f);

    if constexpr (OM == 0) {
        ((float4*)(outExt + (size_t)node * F))[tid] = make_float4(rx, ry, rz, rw);
    } else {
        __nv_bfloat16* Oh = (OM == 1) ? g_Hh : g_H2h;
        __nv_bfloat16* Ol = (OM == 1) ? g_Hl : g_H2l;
        float hx = __bfloat162float(__float2bfloat16(rx));
        float hy = __bfloat162float(__float2bfloat16(ry));
        float hz = __bfloat162float(__float2bfloat16(rz));
        float hw = __bfloat162float(__float2bfloat16(rw));
        size_t d = (size_t)node * F + tid * 4;
        *(uint2*)(Oh + d) = make_uint2(pack_bf2(rx, ry), pack_bf2(rz, rw));
        *(uint2*)(Ol + d) = make_uint2(pack_bf2(rx - hx, ry - hy), pack_bf2(rz - hz, rw - hw));
    }
}

__global__ void combine5_kernel(const float* __restrict__ bias,
                                float* __restrict__ out)
{
    int node = blockIdx.x * 4 + (threadIdx.x >> 5);
    if (node >= NN) return;
    int lane = threadIdx.x & 31;
    if (lane >= 5) return;
    int s = g_rowptr[node], e = g_rowptr[node + 1];
    float acc = 0.f;
    for (int j = s; j < e; j++) acc += g_A[g_col[j] * 5 + lane];
    out[node * 5 + lane] = acc * g_dinv[node] + g_B[node * 5 + lane] + bias[lane];
}

// ================= launch =================
extern "C" void kernel_launch(void* const* d_in, const int* in_sizes, int n_in,
                              void* d_out, int out_size)
{
    const float* x  = (const float*)d_in[0];
    const int*   ei = (const int*)d_in[1];
    const float* Wl1 = (const float*)d_in[2];
    const float* Wr1 = (const float*)d_in[3];
    const float* b1  = (const float*)d_in[4];
    const float* Wl2 = (const float*)d_in[5];
    const float* Wr2 = (const float*)d_in[6];
    const float* b2  = (const float*)d_in[7];
    const float* Wl3 = (const float*)d_in[8];
    const float* Wr3 = (const float*)d_in[9];
    const float* b3  = (const float*)d_in[10];
    const float* Wl4 = (const float*)d_in[11];
    const float* Wr4 = (const float*)d_in[12];
    const float* b4  = (const float*)d_in[13];
    const float* Wl5 = (const float*)d_in[14];
    const float* Wr5 = (const float*)d_in[15];
    const float* b5  = (const float*)d_in[16];

    float* out = (float*)d_out;
    float* out_h   = out;                      // [NN, 256]
    float* out_cls = out + (size_t)NN * 256;   // [NN, 5]

    const int SMEM_SZ = NSTAGE * STG;   // 96 KB -> 2 CTAs/SM
    cudaFuncSetAttribute(bgemm_kernel<0, 1>, cudaFuncAttributeMaxDynamicSharedMemorySize, SMEM_SZ);
    cudaFuncSetAttribute(bgemm_kernel<1, 0>, cudaFuncAttributeMaxDynamicSharedMemorySize, SMEM_SZ);
    cudaFuncSetAttribute(bgemm_kernel<0, 0>, cudaFuncAttributeMaxDynamicSharedMemorySize, SMEM_SZ);

    // ---- CSR build ----
    zero_counts_kernel<<<(NN + 255) / 256, 256>>>();
    count_deg_kernel<<<(EE + 255) / 256, 256>>>(ei);
    scan_deg_kernel<<<1, 1024>>>();
    fill_csr_kernel<<<(EE + 255) / 256, 256>>>(ei);

    // ---- merged weight prep (1 launch) ----
    const int OFF1 = 0;
    const int OFF2L = 2359296, OFF2R = 3538944;
    const int OFF3L = 4718592, OFF3R = 5013504;
    const int OFF4L = 5308416, OFF4R = 5406720;
    WDescs wd;
    // matrix order: Wl1, Wr1, Wl2, Wr2, Wl3, Wr3, Wl4, Wr4
    const float* Ws[8] = {Wl1, Wr1, Wl2, Wr2, Wl3, Wr3, Wl4, Wr4};
    int Ks[8]   = {768, 768, 1536, 1536, 768, 768, 384, 384};
    int Ns[8]   = {1536, 1536, 768, 768, 384, 384, 256, 256};
    int offs[8] = {OFF1, OFF1, OFF2L, OFF2R, OFF3L, OFF3R, OFF4L, OFF4R};
    int kofss[8]= {0, 768, 0, 0, 0, 0, 0, 0};
    int K2s[8]  = {1536, 1536, 1536, 1536, 768, 768, 384, 384};
    int tcur = 0;
    for (int i = 0; i < 8; i++) {
        wd.W[i] = Ws[i]; wd.K[i] = Ks[i]; wd.N[i] = Ns[i];
        wd.off[i] = offs[i]; wd.kofs[i] = kofss[i]; wd.K2[i] = K2s[i];
        wd.tstart[i] = tcur; wd.tilesX[i] = Ks[i] / 32;
        tcur += (Ks[i] / 32) * (Ns[i] / 32);
    }
    wprep_all_kernel<<<tcur, dim3(32, 8)>>>(wd);

    // ---- input prep: fused agg + self split ----
    prep_x_kernel<<<NN, 192>>>(x);

    const int M = NN;
    const int gy = (M + 127) / 128;   // 157

    // ---- Layer 1: fused [agg|x] @ [[Wl],[Wr]] (K=1536) + bias+relu+split ----
    bgemm_kernel<0, 1><<<dim3(12, gy, 1), 256, SMEM_SZ>>>(OFF1, OFF1, b1, M, 1536, 1536);  // -> buf1

    // ---- Layer 2: 1536 -> 768 ----
    bgemm_kernel<1, 0><<<dim3(6, gy, 2), 256, SMEM_SZ>>>(OFF2L, OFF2R, nullptr, M, 1536, 768);
    combine_kernel<768, 1><<<NN, 192>>>(b2, nullptr);     // -> buf0

    // ---- Layer 3: 768 -> 384 ----
    bgemm_kernel<0, 0><<<dim3(3, gy, 2), 256, SMEM_SZ>>>(OFF3L, OFF3R, nullptr, M, 768, 384);
    combine_kernel<384, 2><<<NN, 96>>>(b3, nullptr);      // -> buf1

    // ---- Layer 4: 384 -> 256 (h output fp32) ----
    bgemm_kernel<1, 0><<<dim3(2, gy, 2), 256, SMEM_SZ>>>(OFF4L, OFF4R, nullptr, M, 384, 256);
    combine_kernel<256, 0><<<NN, 64>>>(b4, out_h);        // -> d_out h region

    // ---- Layer 5: 256 -> 5 (no relu) ----
    gemm_small_kernel<<<dim3((NN * 5 + 255) / 256, 2), 256>>>(out_h, Wl5, Wr5, M, 256, 5);
    combine5_kernel<<<(NN + 3) / 4, 128>>>(b5, out_cls);
}

// round 13
// speedup vs baseline: 2.8500x; 1.9783x over previous
#include <cuda_runtime.h>
#include <cuda_fp16.h>
#include <cstdint>

#define NN 20000
#define EE 320000

// ================= static scratch =================
__device__ __align__(16) float g_A[NN * 1536];    // GEMM fp32 out (z=0)
__device__ __align__(16) float g_B[NN * 1536];    // GEMM fp32 out (z=1)
// fp16 activation buffers (ping-pong)
__device__ __align__(16) __half g_H1[NN * 1536];
__device__ __align__(16) __half g_H2[NN * 1536];
// fp16 transposed weights, manual offsets (total 5505024 elems)
__device__ __align__(16) __half g_Wh[5505024];
__device__ int   g_deg[NN];
__device__ int   g_fill[NN];
__device__ int   g_rowptr[NN + 1];
__device__ int   g_col[EE];
__device__ float g_dinv[NN];

// ================= helpers (baseline PTX, sm_80+) =================
__device__ __forceinline__ uint32_t smem_u32(const void* p) {
    uint32_t a;
    asm("{ .reg .u64 t; cvta.to.shared.u64 t, %1; cvt.u32.u64 %0, t; }" : "=r"(a) : "l"(p));
    return a;
}
__device__ __forceinline__ void ldm_x4(uint32_t* r, uint32_t addr) {
    asm volatile("ldmatrix.sync.aligned.m8n8.x4.shared.b16 {%0,%1,%2,%3}, [%4];"
        : "=r"(r[0]), "=r"(r[1]), "=r"(r[2]), "=r"(r[3]) : "r"(addr));
}
__device__ __forceinline__ void mma16816(float* c, const uint32_t* a, const uint32_t* b) {
    asm volatile("mma.sync.aligned.m16n8k16.row.col.f32.f16.f16.f32 "
        "{%0,%1,%2,%3}, {%4,%5,%6,%7}, {%8,%9}, {%0,%1,%2,%3};"
        : "+f"(c[0]), "+f"(c[1]), "+f"(c[2]), "+f"(c[3])
        : "r"(a[0]), "r"(a[1]), "r"(a[2]), "r"(a[3]), "r"(b[0]), "r"(b[1]));
}
__device__ __forceinline__ uint32_t sw128(uint32_t off) {
    return off ^ ((off >> 3) & 0x70);
}
__device__ __forceinline__ uint32_t pack_h2(float a, float b) {
    __half2 v = __floats2half2_rn(a, b);
    return *(uint32_t*)&v;
}
#define CP_ASYNC16(saddr, gptr) \
    asm volatile("cp.async.cg.shared.global [%0], [%1], 16;" :: "r"(saddr), "l"(gptr))
#define CP_COMMIT() asm volatile("cp.async.commit_group;")
#define CP_WAIT1()  asm volatile("cp.async.wait_group 1;")

// ================= CSR construction (edge_index int32) =================
__global__ void zero_counts_kernel() {
    int i = blockIdx.x * blockDim.x + threadIdx.x;
    if (i < NN) { g_deg[i] = 0; g_fill[i] = 0; }
}
__global__ void count_deg_kernel(const int* __restrict__ ei) {
    int e = blockIdx.x * blockDim.x + threadIdx.x;
    if (e < EE) {
        int dst = ei[EE + e];
        if ((unsigned)dst < NN) atomicAdd(&g_deg[dst], 1);
    }
}
// shuffle-based single-block scan: 1024 threads x 20 elems each
__global__ __launch_bounds__(1024) void scan_deg_kernel() {
    const int PER = 20;
    const int tid = threadIdx.x;
    const int lane = tid & 31;
    const int warp = tid >> 5;
    const int base = tid * PER;

    int incl[PER];
    int s = 0;
#pragma unroll
    for (int i = 0; i < PER; i++) {
        int idx = base + i;
        int v = (idx < NN) ? g_deg[idx] : 0;
        s += v;
        incl[i] = s;
    }
    int ssum = s;
#pragma unroll
    for (int off = 1; off < 32; off <<= 1) {
        int t = __shfl_up_sync(0xffffffffu, ssum, off);
        if (lane >= off) ssum += t;
    }
    __shared__ int wsum[32];
    if (lane == 31) wsum[warp] = ssum;
    __syncthreads();
    if (warp == 0) {
        int w = wsum[lane];
#pragma unroll
        for (int off = 1; off < 32; off <<= 1) {
            int t = __shfl_up_sync(0xffffffffu, w, off);
            if (lane >= off) w += t;
        }
        wsum[lane] = w;
    }
    __syncthreads();
    const int offset = (warp ? wsum[warp - 1] : 0) + (ssum - s);
    if (tid == 0) g_rowptr[0] = 0;
#pragma unroll
    for (int i = 0; i < PER; i++) {
        int idx = base + i;
        if (idx < NN) {
            g_rowptr[idx + 1] = offset + incl[i];
            int d = incl[i] - (i ? incl[i - 1] : 0);
            g_dinv[idx] = 1.0f / fmaxf((float)d, 1.0f);
        }
    }
}
__global__ void fill_csr_kernel(const int* __restrict__ ei) {
    int e = blockIdx.x * blockDim.x + threadIdx.x;
    if (e < EE) {
        int src = ei[e];
        int dst = ei[EE + e];
        if ((unsigned)dst < NN && (unsigned)src < NN) {
            int p = atomicAdd(&g_fill[dst], 1);
            g_col[g_rowptr[dst] + p] = src;
        }
    }
}

// ============ merged weight prep: 8 matrices, one launch, fp16 ============
struct WDescs {
    const float* W[8];
    int N[8], off[8], kofs[8], K2[8], tstart[8], tilesX[8];
};
__global__ void wprep_all_kernel(WDescs d) {
    __shared__ float tile[32][33];
    const int bid = blockIdx.x;
    int m = 0;
#pragma unroll
    for (int i = 1; i < 8; i++)
        if (bid >= d.tstart[i]) m = i;
    const int lt = bid - d.tstart[m];
    const int k0 = (lt % d.tilesX[m]) * 32;
    const int n0 = (lt / d.tilesX[m]) * 32;
    const float* W = d.W[m];
    const int N = d.N[m], off = d.off[m], kofs = d.kofs[m], K2 = d.K2[m];
    const int tx = threadIdx.x, ty = threadIdx.y;   // 32 x 8
#pragma unroll
    for (int r = 0; r < 4; r++)
        tile[ty + r * 8][tx] = W[(size_t)(k0 + ty + r * 8) * N + n0 + tx];
    __syncthreads();
#pragma unroll
    for (int r = 0; r < 4; r++) {
        int n = n0 + ty + r * 8;
        float w = tile[tx][ty + r * 8];
        size_t dd = (size_t)off + (size_t)n * K2 + kofs + k0 + tx;
        g_Wh[dd] = __float2half_rn(w);
    }
}

// fused: mean-aggregate neighbors -> fp16 -> cols [0,768);
//        own x row -> fp16 -> cols [768,1536). Block per node, 192 threads.
__global__ __launch_bounds__(192) void prep_x_kernel(const float* __restrict__ x) {
    const int node = blockIdx.x;
    const int tid = threadIdx.x;
    const int s = g_rowptr[node];
    const int e = g_rowptr[node + 1];
    float4 acc = make_float4(0.f, 0.f, 0.f, 0.f);
    __shared__ int nb[192];
    for (int base = s; base < e; base += 192) {
        int cnt = min(192, e - base);
        if (tid < cnt) nb[tid] = g_col[base + tid];
        __syncthreads();
        for (int j = 0; j < cnt; j++) {
            float4 v = ((const float4*)(x + (size_t)nb[j] * 768))[tid];
            acc.x += v.x; acc.y += v.y; acc.z += v.z; acc.w += v.w;
        }
        __syncthreads();
    }
    const float di = g_dinv[node];
    {
        size_t d = (size_t)node * 1536 + tid * 4;
        *(uint2*)(g_H1 + d) = make_uint2(pack_h2(acc.x * di, acc.y * di),
                                         pack_h2(acc.z * di, acc.w * di));
    }
    {
        float4 v = ((const float4*)(x + (size_t)node * 768))[tid];
        size_t d = (size_t)node * 1536 + 768 + tid * 4;
        *(uint2*)(g_H1 + d) = make_uint2(pack_h2(v.x, v.y), pack_h2(v.z, v.w));
    }
}

// ======= fp16 HMMA GEMM: BM=128, BN=128, BK=64, 3-stage, 2 CTAs/SM =======
// AB: 0 -> A from g_H1, 1 -> A from g_H2
// EPI: 0 -> fp32 out to (z ? g_B : g_A); gridDim.z = 2, weights woff_l/woff_r
// EPI: 1 -> fused bias+relu+fp16 out to the OTHER buffer; gridDim.z = 1
// stage: A(16K) | B(16K) = 32KB; rows 128B wide, SW128 swizzle.
#define STG 32768
#define NSTAGE 3
template <int AB, int EPI>
__global__ __launch_bounds__(256, 2) void bgemm_kernel(
    int woff_l, int woff_r, const float* __restrict__ bias,
    int M, int Kd, int Nd)
{
    extern __shared__ __align__(1024) uint8_t dsm[];
    const __half* Ain = AB ? g_H2 : g_H1;
    const int tid = threadIdx.x;
    const int wid = tid >> 5;
    const int lane = tid & 31;
    const int m0 = blockIdx.y * 128;
    const int n0 = blockIdx.x * 128;
    const int woff = blockIdx.z ? woff_r : woff_l;
    const int warp_m = (wid & 1) * 64;
    const int warp_n = (wid >> 1) * 32;
    const uint32_t sb = smem_u32(dsm);

    // loads: 2 threads/row; q selects 64B half of the 128B row
    const int lrow = tid >> 1;
    const int q = tid & 1;
    const int arow = min(m0 + lrow, M - 1);
    const __half* gA = Ain + (size_t)arow * Kd + q * 32;
    const __half* gB = g_Wh + woff + (size_t)(n0 + lrow) * Kd + q * 32;
    const uint32_t dbase = lrow * 128 + q * 64;

    float acc[4][4][4];
#pragma unroll
    for (int mi = 0; mi < 4; mi++)
#pragma unroll
        for (int ni = 0; ni < 4; ni++)
#pragma unroll
            for (int qq = 0; qq < 4; qq++) acc[mi][ni][qq] = 0.f;

    const int sub = lane >> 3;
    const int lr = lane & 7;
    const int nch = Kd >> 6;

#define ISSUE64(stadr, kofs) do { \
        uint32_t _sa = (stadr); \
        _Pragma("unroll") \
        for (int j = 0; j < 4; j++) { \
            uint32_t o = sw128(dbase + j * 16); \
            CP_ASYNC16(_sa + o,         gA + (kofs) + j * 8); \
            CP_ASYNC16(_sa + 16384 + o, gB + (kofs) + j * 8); \
        } \
    } while (0)

    ISSUE64(sb, 0);
    CP_COMMIT();
    if (1 < nch) ISSUE64(sb + STG, 64);
    CP_COMMIT();

    int st = 0;
    int st2 = 2;
    for (int ch = 0; ch < nch; ch++) {
        CP_WAIT1();
        __syncthreads();

        if (ch + 2 < nch) ISSUE64(sb + st2 * STG, (ch + 2) << 6);
        CP_COMMIT();

        const uint32_t sA = sb + st * STG;
        const uint32_t sB = sA + 16384;

#pragma unroll
        for (int ks = 0; ks < 4; ks++) {
            uint32_t bh[2][4];
#pragma unroll
            for (int np = 0; np < 2; np++) {
                int row = warp_n + np * 16 + (sub >> 1) * 8 + lr;
                uint32_t kb = ks * 32 + (sub & 1) * 16;
                ldm_x4(bh[np], sB + sw128(row * 128 + kb));
            }
#pragma unroll
            for (int mi = 0; mi < 4; mi++) {
                uint32_t ah[4];
                int row = warp_m + mi * 16 + (sub & 1) * 8 + lr;
                uint32_t kb = ks * 32 + (sub >> 1) * 16;
                ldm_x4(ah, sA + sw128(row * 128 + kb));
#pragma unroll
                for (int ni = 0; ni < 4; ni++)
                    mma16816(acc[mi][ni], ah, &bh[ni >> 1][(ni & 1) * 2]);
            }
        }
        st = (st == 2) ? 0 : st + 1;
        st2 = (st2 == 2) ? 0 : st2 + 1;
    }

    // ---- epilogue ----
    const int g = lane >> 2;
    const int t = lane & 3;
    if constexpr (EPI == 0) {
        float* C = blockIdx.z ? g_B : g_A;
#pragma unroll
        for (int mi = 0; mi < 4; mi++) {
            int r0 = m0 + warp_m + mi * 16 + g;
            int r1 = r0 + 8;
#pragma unroll
            for (int ni = 0; ni < 4; ni++) {
                int col = n0 + warp_n + ni * 8 + t * 2;
                if (r0 < M) *(float2*)(C + (size_t)r0 * Nd + col) = make_float2(acc[mi][ni][0], acc[mi][ni][1]);
                if (r1 < M) *(float2*)(C + (size_t)r1 * Nd + col) = make_float2(acc[mi][ni][2], acc[mi][ni][3]);
            }
        }
    } else {
        __half* O = AB ? g_H1 : g_H2;
#pragma unroll
        for (int mi = 0; mi < 4; mi++) {
            int r0 = m0 + warp_m + mi * 16 + g;
            int r1 = r0 + 8;
#pragma unroll
            for (int ni = 0; ni < 4; ni++) {
                int col = n0 + warp_n + ni * 8 + t * 2;
                float b0 = bias[col], b1v = bias[col + 1];
                float v0 = fmaxf(acc[mi][ni][0] + b0, 0.f);
                float v1 = fmaxf(acc[mi][ni][1] + b1v, 0.f);
                float v2 = fmaxf(acc[mi][ni][2] + b0, 0.f);
                float v3 = fmaxf(acc[mi][ni][3] + b1v, 0.f);
                if (r0 < M) *(uint32_t*)(O + (size_t)r0 * Nd + col) = pack_h2(v0, v1);
                if (r1 < M) *(uint32_t*)(O + (size_t)r1 * Nd + col) = pack_h2(v2, v3);
            }
        }
    }
}

// ================= small-N GEMM for the final 256->5 linear =================
__global__ void gemm_small_kernel(const float* __restrict__ Aext,
                                  const float* __restrict__ W0,
                                  const float* __restrict__ W1,
                                  int M, int Kd, int Nd)
{
    const float* W = blockIdx.y ? W1 : W0;
    float* C = blockIdx.y ? g_B : g_A;
    int idx = blockIdx.x * blockDim.x + threadIdx.x;
    if (idx >= M * Nd) return;
    int row = idx / Nd, c = idx % Nd;
    const float* a = Aext + (size_t)row * Kd;
    float acc = 0.f;
    for (int k = 0; k < Kd; k++) acc += a[k] * W[k * Nd + c];
    C[idx] = acc;
}

// ================= combine (layers 2-4): r = relu(di*agg(g_A) + g_B + b) ===
// OM: 0 -> fp32 float4 to ext; 1 -> fp16 to g_H1; 2 -> fp16 to g_H2
template <int F, int OM>
__global__ void combine_kernel(const float* __restrict__ bias,
                               float* __restrict__ outExt)
{
    constexpr int NT = F / 4;
    const int node = blockIdx.x;
    const int tid = threadIdx.x;
    const int s = g_rowptr[node];
    const int e = g_rowptr[node + 1];

    float4 acc = make_float4(0.f, 0.f, 0.f, 0.f);
    __shared__ int nb[NT];
    for (int base = s; base < e; base += NT) {
        int cnt = min(NT, e - base);
        if (tid < cnt) nb[tid] = g_col[base + tid];
        __syncthreads();
        for (int j = 0; j < cnt; j++) {
            float4 v = ((const float4*)(g_A + (size_t)nb[j] * F))[tid];
            acc.x += v.x; acc.y += v.y; acc.z += v.z; acc.w += v.w;
        }
        __syncthreads();
    }

    const float di = g_dinv[node];
    float4 sv = ((const float4*)(g_B + (size_t)node * F))[tid];
    float4 bv = ((const float4*)bias)[tid];
    float rx = fmaxf(acc.x * di + sv.x + bv.x, 0.f);
    float ry = fmaxf(acc.y * di + sv.y + bv.y, 0.f);
    float rz = fmaxf(acc.z * di + sv.z + bv.z, 0.f);
    float rw = fmaxf(acc.w * di + sv.w + bv.w, 0.f);

    if constexpr (OM == 0) {
        ((float4*)(outExt + (size_t)node * F))[tid] = make_float4(rx, ry, rz, rw);
    } else {
        __half* O = (OM == 1) ? g_H1 : g_H2;
        size_t d = (size_t)node * F + tid * 4;
        *(uint2*)(O + d) = make_uint2(pack_h2(rx, ry), pack_h2(rz, rw));
    }
}

__global__ void combine5_kernel(const float* __restrict__ bias,
                                float* __restrict__ out)
{
    int node = blockIdx.x * 4 + (threadIdx.x >> 5);
    if (node >= NN) return;
    int lane = threadIdx.x & 31;
    if (lane >= 5) return;
    int s = g_rowptr[node], e = g_rowptr[node + 1];
    float acc = 0.f;
    for (int j = s; j < e; j++) acc += g_A[g_col[j] * 5 + lane];
    out[node * 5 + lane] = acc * g_dinv[node] + g_B[node * 5 + lane] + bias[lane];
}

// ================= launch =================
extern "C" void kernel_launch(void* const* d_in, const int* in_sizes, int n_in,
                              void* d_out, int out_size)
{
    const float* x  = (const float*)d_in[0];
    const int*   ei = (const int*)d_in[1];
    const float* Wl1 = (const float*)d_in[2];
    const float* Wr1 = (const float*)d_in[3];
    const float* b1  = (const float*)d_in[4];
    const float* Wl2 = (const float*)d_in[5];
    const float* Wr2 = (const float*)d_in[6];
    const float* b2  = (const float*)d_in[7];
    const float* Wl3 = (const float*)d_in[8];
    const float* Wr3 = (const float*)d_in[9];
    const float* b3  = (const float*)d_in[10];
    const float* Wl4 = (const float*)d_in[11];
    const float* Wr4 = (const float*)d_in[12];
    const float* b4  = (const float*)d_in[13];
    const float* Wl5 = (const float*)d_in[14];
    const float* Wr5 = (const float*)d_in[15];
    const float* b5  = (const float*)d_in[16];

    float* out = (float*)d_out;
    float* out_h   = out;                      // [NN, 256]
    float* out_cls = out + (size_t)NN * 256;   // [NN, 5]

    const int SMEM_SZ = NSTAGE * STG;   // 96 KB -> 2 CTAs/SM
    cudaFuncSetAttribute(bgemm_kernel<0, 1>, cudaFuncAttributeMaxDynamicSharedMemorySize, SMEM_SZ);
    cudaFuncSetAttribute(bgemm_kernel<1, 0>, cudaFuncAttributeMaxDynamicSharedMemorySize, SMEM_SZ);
    cudaFuncSetAttribute(bgemm_kernel<0, 0>, cudaFuncAttributeMaxDynamicSharedMemorySize, SMEM_SZ);

    // ---- CSR build ----
    zero_counts_kernel<<<(NN + 255) / 256, 256>>>();
    count_deg_kernel<<<(EE + 255) / 256, 256>>>(ei);
    scan_deg_kernel<<<1, 1024>>>();
    fill_csr_kernel<<<(EE + 255) / 256, 256>>>(ei);

    // ---- merged weight prep (1 launch, fp16) ----
    const int OFF1 = 0;
    const int OFF2L = 2359296, OFF2R = 3538944;
    const int OFF3L = 4718592, OFF3R = 5013504;
    const int OFF4L = 5308416, OFF4R = 5406720;
    WDescs wd;
    const float* Ws[8] = {Wl1, Wr1, Wl2, Wr2, Wl3, Wr3, Wl4, Wr4};
    int Ks[8]   = {768, 768, 1536, 1536, 768, 768, 384, 384};
    int Ns[8]   = {1536, 1536, 768, 768, 384, 384, 256, 256};
    int offs[8] = {OFF1, OFF1, OFF2L, OFF2R, OFF3L, OFF3R, OFF4L, OFF4R};
    int kofss[8]= {0, 768, 0, 0, 0, 0, 0, 0};
    int K2s[8]  = {1536, 1536, 1536, 1536, 768, 768, 384, 384};
    int tcur = 0;
    for (int i = 0; i < 8; i++) {
        wd.W[i] = Ws[i]; wd.N[i] = Ns[i];
        wd.off[i] = offs[i]; wd.kofs[i] = kofss[i]; wd.K2[i] = K2s[i];
        wd.tstart[i] = tcur; wd.tilesX[i] = Ks[i] / 32;
        tcur += (Ks[i] / 32) * (Ns[i] / 32);
    }
    wprep_all_kernel<<<tcur, dim3(32, 8)>>>(wd);

    // ---- input prep: fused agg + self, fp16 ----
    prep_x_kernel<<<NN, 192>>>(x);

    const int M = NN;
    const int gy = (M + 127) / 128;   // 157

    // ---- Layer 1: fused [agg|x] @ [[Wl],[Wr]] (K=1536) + bias+relu -> fp16 ----
    bgemm_kernel<0, 1><<<dim3(12, gy, 1), 256, SMEM_SZ>>>(OFF1, OFF1, b1, M, 1536, 1536);  // -> g_H2

    // ---- Layer 2: 1536 -> 768 ----
    bgemm_kernel<1, 0><<<dim3(6, gy, 2), 256, SMEM_SZ>>>(OFF2L, OFF2R, nullptr, M, 1536, 768);
    combine_kernel<768, 1><<<NN, 192>>>(b2, nullptr);     // -> g_H1

    // ---- Layer 3: 768 -> 384 ----
    bgemm_kernel<0, 0><<<dim3(3, gy, 2), 256, SMEM_SZ>>>(OFF3L, OFF3R, nullptr, M, 768, 384);
    combine_kernel<384, 2><<<NN, 96>>>(b3, nullptr);      // -> g_H2

    // ---- Layer 4: 384 -> 256 (h output fp32) ----
    bgemm_kernel<1, 0><<<dim3(2, gy, 2), 256, SMEM_SZ>>>(OFF4L, OFF4R, nullptr, M, 384, 256);
    combine_kernel<256, 0><<<NN, 64>>>(b4, out_h);        // -> d_out h region

    // ---- Layer 5: 256 -> 5 (no relu) ----
    gemm_small_kernel<<<dim3((NN * 5 + 255) / 256, 2), 256>>>(out_h, Wl5, Wr5, M, 256, 5);
    combine5_kernel<<<(NN + 3) / 4, 128>>>(b5, out_cls);
}